// round 1
// baseline (speedup 1.0000x reference)
#include <cuda_runtime.h>
#include <math.h>

// Problem constants (fixed shapes)
#define BS   2
#define SEQ  2048
#define EMB  1024
#define NH   16
#define HD   64
#define F3   3072   // 3*EMB

// Scratch (device globals: allocation-free rule)
__device__ float g_qkv[BS * SEQ * F3];   // [4096, 3072]  (b,s major; f = h*192 + c)
__device__ float g_att[BS * SEQ * EMB];  // [4096, 1024]

// ---------------------------------------------------------------------------
// GEMM: C[m,n] = sum_k A[m,k] * B[n,k] (+ bias[n])
// BM=BN=128, BK=16, 256 threads, 8x8 register micro-tile.
// ---------------------------------------------------------------------------
template <bool HAS_BIAS>
__global__ __launch_bounds__(256, 2)
void gemm_tn(const float* __restrict__ A, const float* __restrict__ B,
             const float* __restrict__ bias, float* __restrict__ C,
             int N, int K) {
    __shared__ float As[16][132];   // [kk][m], padded row (132*4 % 16 == 0)
    __shared__ float Bs[16][132];   // [kk][n]

    const int t  = threadIdx.x;
    const int tx = t & 15;
    const int ty = t >> 4;
    const int m0 = blockIdx.y * 128;
    const int n0 = blockIdx.x * 128;

    float acc[8][8];
#pragma unroll
    for (int i = 0; i < 8; i++)
#pragma unroll
        for (int j = 0; j < 8; j++) acc[i][j] = 0.0f;

    for (int k0 = 0; k0 < K; k0 += 16) {
        // Load 128x16 A-tile and B-tile (512 float4 each; 2 per thread)
#pragma unroll
        for (int i = 0; i < 2; i++) {
            int idx = 2 * t + i;
            int row = idx >> 2;
            int q   = idx & 3;
            float4 av = *(const float4*)(A + (size_t)(m0 + row) * K + k0 + 4 * q);
            As[4 * q + 0][row] = av.x;
            As[4 * q + 1][row] = av.y;
            As[4 * q + 2][row] = av.z;
            As[4 * q + 3][row] = av.w;
            float4 bv = *(const float4*)(B + (size_t)(n0 + row) * K + k0 + 4 * q);
            Bs[4 * q + 0][row] = bv.x;
            Bs[4 * q + 1][row] = bv.y;
            Bs[4 * q + 2][row] = bv.z;
            Bs[4 * q + 3][row] = bv.w;
        }
        __syncthreads();

#pragma unroll
        for (int kk = 0; kk < 16; kk++) {
            float4 a0 = *(const float4*)&As[kk][8 * ty];
            float4 a1 = *(const float4*)&As[kk][8 * ty + 4];
            float4 b0 = *(const float4*)&Bs[kk][8 * tx];
            float4 b1 = *(const float4*)&Bs[kk][8 * tx + 4];
            float a[8] = {a0.x, a0.y, a0.z, a0.w, a1.x, a1.y, a1.z, a1.w};
            float b[8] = {b0.x, b0.y, b0.z, b0.w, b1.x, b1.y, b1.z, b1.w};
#pragma unroll
            for (int ii = 0; ii < 8; ii++)
#pragma unroll
                for (int jj = 0; jj < 8; jj++) acc[ii][jj] += a[ii] * b[jj];
        }
        __syncthreads();
    }

    // Epilogue
#pragma unroll
    for (int ii = 0; ii < 8; ii++) {
        int m = m0 + 8 * ty + ii;
        float* cp = C + (size_t)m * N + n0 + 8 * tx;
#pragma unroll
        for (int jj = 0; jj < 8; jj++) {
            float v = acc[ii][jj];
            if (HAS_BIAS) v += bias[n0 + 8 * tx + jj];
            cp[jj] = v;
        }
    }
}

// ---------------------------------------------------------------------------
// Causal flash attention, fp32. One block = one 64-row query tile of one head.
// BM=BN=64, HD=64, 256 threads (16x16), 4x4 micro-tiles.
// qkv layout: [b*SEQ + s][h*192 + c], c: q=[0,64), k=[64,128), v=[128,192)
// ---------------------------------------------------------------------------
#define ATTN_SMEM (4 * 64 * 68 * 4)

__global__ __launch_bounds__(256)
void attn_kernel(const float* __restrict__ qkv, float* __restrict__ att) {
    extern __shared__ float sm[];
    float* QsT = sm;                // [d][r]  stride 68
    float* KsT = sm + 64 * 68;      // [d][c]
    float* Vs  = sm + 2 * 64 * 68;  // [n][d]
    float* PsT = sm + 3 * 64 * 68;  // [n][r]

    const int t  = threadIdx.x;
    const int tx = t & 15;
    const int ty = t >> 4;
    const int it = blockIdx.x;      // query tile 0..31
    const int h  = blockIdx.y;
    const int b  = blockIdx.z;
    const size_t base = (size_t)b * SEQ * F3 + (size_t)h * 192;

    // Load Q tile transposed: QsT[d][r]
#pragma unroll
    for (int i = 0; i < 4; i++) {
        int idx = t + 256 * i;      // 0..1023
        int r = idx >> 4;
        int q = idx & 15;
        float4 v = *(const float4*)(qkv + base + (size_t)(it * 64 + r) * F3 + 4 * q);
        QsT[(4 * q + 0) * 68 + r] = v.x;
        QsT[(4 * q + 1) * 68 + r] = v.y;
        QsT[(4 * q + 2) * 68 + r] = v.z;
        QsT[(4 * q + 3) * 68 + r] = v.w;
    }

    float m_i[4], l_i[4], acc[4][4];
#pragma unroll
    for (int i = 0; i < 4; i++) {
        m_i[i] = -1e30f;
        l_i[i] = 0.0f;
#pragma unroll
        for (int j = 0; j < 4; j++) acc[i][j] = 0.0f;
    }

    for (int jt = 0; jt <= it; jt++) {
        __syncthreads();   // previous iter's PV reads done before overwrite

        // Load K tile transposed (KsT[d][c]) and V tile direct (Vs[n][d])
#pragma unroll
        for (int i = 0; i < 4; i++) {
            int idx = t + 256 * i;
            int r = idx >> 4;
            int q = idx & 15;
            const float* kp = qkv + base + (size_t)(jt * 64 + r) * F3 + 64 + 4 * q;
            float4 kv = *(const float4*)kp;
            KsT[(4 * q + 0) * 68 + r] = kv.x;
            KsT[(4 * q + 1) * 68 + r] = kv.y;
            KsT[(4 * q + 2) * 68 + r] = kv.z;
            KsT[(4 * q + 3) * 68 + r] = kv.w;
            const float* vp = kp + 64;
            float4 vv = *(const float4*)vp;
            *(float4*)&Vs[r * 68 + 4 * q] = vv;
        }
        __syncthreads();

        // S = Q K^T (4x4 per thread)
        float s[4][4];
#pragma unroll
        for (int ii = 0; ii < 4; ii++)
#pragma unroll
            for (int jj = 0; jj < 4; jj++) s[ii][jj] = 0.0f;

#pragma unroll 8
        for (int d = 0; d < 64; d++) {
            float4 q4 = *(const float4*)&QsT[d * 68 + 4 * ty];
            float4 k4 = *(const float4*)&KsT[d * 68 + 4 * tx];
            float qa[4] = {q4.x, q4.y, q4.z, q4.w};
            float ka[4] = {k4.x, k4.y, k4.z, k4.w};
#pragma unroll
            for (int ii = 0; ii < 4; ii++)
#pragma unroll
                for (int jj = 0; jj < 4; jj++) s[ii][jj] += qa[ii] * ka[jj];
        }

        const float scale = 0.125f;  // 1/sqrt(64)
#pragma unroll
        for (int ii = 0; ii < 4; ii++)
#pragma unroll
            for (int jj = 0; jj < 4; jj++) {
                s[ii][jj] *= scale;
                if (jt == it && (4 * tx + jj) > (4 * ty + ii)) s[ii][jj] = -1e30f;
            }

        // Row max (reduce across the 16 tx lanes of this row group)
        float mloc[4];
#pragma unroll
        for (int ii = 0; ii < 4; ii++) {
            float mv = s[ii][0];
            mv = fmaxf(mv, s[ii][1]);
            mv = fmaxf(mv, s[ii][2]);
            mv = fmaxf(mv, s[ii][3]);
            mloc[ii] = mv;
        }
#pragma unroll
        for (int off = 8; off >= 1; off >>= 1)
#pragma unroll
            for (int ii = 0; ii < 4; ii++)
                mloc[ii] = fmaxf(mloc[ii], __shfl_xor_sync(0xffffffffu, mloc[ii], off));

        float mnew[4], alpha[4], rsum[4];
#pragma unroll
        for (int ii = 0; ii < 4; ii++) {
            mnew[ii]  = fmaxf(m_i[ii], mloc[ii]);
            alpha[ii] = __expf(m_i[ii] - mnew[ii]);
        }

        // P = exp(S - mnew), write transposed PsT[c][r], accumulate row sums
        float p[4][4];
#pragma unroll
        for (int ii = 0; ii < 4; ii++) {
            float rs = 0.0f;
#pragma unroll
            for (int jj = 0; jj < 4; jj++) {
                float pv = __expf(s[ii][jj] - mnew[ii]);
                p[ii][jj] = pv;
                rs += pv;
            }
            rsum[ii] = rs;
        }
#pragma unroll
        for (int off = 8; off >= 1; off >>= 1)
#pragma unroll
            for (int ii = 0; ii < 4; ii++)
                rsum[ii] += __shfl_xor_sync(0xffffffffu, rsum[ii], off);

#pragma unroll
        for (int ii = 0; ii < 4; ii++) {
            l_i[ii] = l_i[ii] * alpha[ii] + rsum[ii];
            m_i[ii] = mnew[ii];
#pragma unroll
            for (int jj = 0; jj < 4; jj++) acc[ii][jj] *= alpha[ii];
        }

#pragma unroll
        for (int jj = 0; jj < 4; jj++) {
            float4 pc = make_float4(p[0][jj], p[1][jj], p[2][jj], p[3][jj]);
            *(float4*)&PsT[(4 * tx + jj) * 68 + 4 * ty] = pc;
        }
        __syncthreads();

        // O += P V (4x4 per thread; acc cols are head-dim)
#pragma unroll 8
        for (int n = 0; n < 64; n++) {
            float4 p4 = *(const float4*)&PsT[n * 68 + 4 * ty];
            float4 v4 = *(const float4*)&Vs[n * 68 + 4 * tx];
            float pa[4] = {p4.x, p4.y, p4.z, p4.w};
            float va[4] = {v4.x, v4.y, v4.z, v4.w};
#pragma unroll
            for (int ii = 0; ii < 4; ii++)
#pragma unroll
                for (int jj = 0; jj < 4; jj++) acc[ii][jj] += pa[ii] * va[jj];
        }
    }

    // Epilogue: O / l  ->  att[(b*SEQ + row)*EMB + h*64 + d]
#pragma unroll
    for (int ii = 0; ii < 4; ii++) {
        int grow = it * 64 + 4 * ty + ii;
        float inv_l = 1.0f / l_i[ii];
        float4 o = make_float4(acc[ii][0] * inv_l, acc[ii][1] * inv_l,
                               acc[ii][2] * inv_l, acc[ii][3] * inv_l);
        *(float4*)(att + ((size_t)b * SEQ + grow) * EMB + h * 64 + 4 * tx) = o;
    }
}

// ---------------------------------------------------------------------------
// Launch
// ---------------------------------------------------------------------------
extern "C" void kernel_launch(void* const* d_in, const int* in_sizes, int n_in,
                              void* d_out, int out_size) {
    const float* x      = (const float*)d_in[0];  // [2,2048,1024]
    const float* w_qkv  = (const float*)d_in[1];  // [3072,1024]
    const float* w_out  = (const float*)d_in[2];  // [1024,1024]
    const float* b_out  = (const float*)d_in[3];  // [1024]
    float* out = (float*)d_out;

    float *qkv, *att;
    cudaGetSymbolAddress((void**)&qkv, g_qkv);
    cudaGetSymbolAddress((void**)&att, g_att);

    cudaFuncSetAttribute(attn_kernel,
                         cudaFuncAttributeMaxDynamicSharedMemorySize, ATTN_SMEM);

    // 1) QKV projection: [4096,3072] = x[4096,1024] * w_qkv^T
    gemm_tn<false><<<dim3(F3 / 128, (BS * SEQ) / 128), 256>>>(
        x, w_qkv, nullptr, qkv, F3, EMB);

    // 2) Causal flash attention
    attn_kernel<<<dim3(SEQ / 64, NH, BS), 256, ATTN_SMEM>>>(qkv, att);

    // 3) Output projection + bias
    gemm_tn<true><<<dim3(EMB / 128, (BS * SEQ) / 128), 256>>>(
        att, w_out, b_out, out, EMB, EMB);
}

// round 3
// speedup vs baseline: 1.3464x; 1.3464x over previous
#include <cuda_runtime.h>
#include <cuda_bf16.h>
#include <cstdint>
#include <math.h>

// Problem constants (fixed shapes)
#define BS   2
#define SEQ  2048
#define EMB  1024
#define NH   16
#define HD   64
#define F3   3072   // 3*EMB
#define ROWS (BS * SEQ)   // 4096

// ---------------------------------------------------------------------------
// Scratch (device globals: allocation-free rule)
// ---------------------------------------------------------------------------
__device__ float g_qkv[ROWS * F3];              // fp32 qkv  [4096,3072]
__device__ float g_att[ROWS * EMB];             // fp32 attn out [4096,1024]
__device__ __nv_bfloat16 g_x_hi[ROWS * EMB];
__device__ __nv_bfloat16 g_x_lo[ROWS * EMB];
__device__ __nv_bfloat16 g_wqkv_hi[F3 * EMB];
__device__ __nv_bfloat16 g_wqkv_lo[F3 * EMB];
__device__ __nv_bfloat16 g_wout_hi[EMB * EMB];
__device__ __nv_bfloat16 g_wout_lo[EMB * EMB];
__device__ __nv_bfloat16 g_att_hi[ROWS * EMB];
__device__ __nv_bfloat16 g_att_lo[ROWS * EMB];

// ---------------------------------------------------------------------------
// helpers
// ---------------------------------------------------------------------------
__device__ __forceinline__ uint32_t smem_u32(const void* p) {
    uint32_t a;
    asm("{ .reg .u64 t; cvta.to.shared.u64 t, %1; cvt.u32.u64 %0, t; }" : "=r"(a) : "l"(p));
    return a;
}

__device__ __forceinline__ void ldsm_x4(uint32_t addr, uint32_t r[4]) {
    asm volatile("ldmatrix.sync.aligned.m8n8.x4.shared.b16 {%0,%1,%2,%3}, [%4];"
                 : "=r"(r[0]), "=r"(r[1]), "=r"(r[2]), "=r"(r[3]) : "r"(addr));
}

__device__ __forceinline__ void mma16816(float c[4], const uint32_t a[4],
                                         const uint32_t b0, const uint32_t b1) {
    asm volatile(
        "mma.sync.aligned.m16n8k16.row.col.f32.bf16.bf16.f32 "
        "{%0,%1,%2,%3}, {%4,%5,%6,%7}, {%8,%9}, {%0,%1,%2,%3};"
        : "+f"(c[0]), "+f"(c[1]), "+f"(c[2]), "+f"(c[3])
        : "r"(a[0]), "r"(a[1]), "r"(a[2]), "r"(a[3]), "r"(b0), "r"(b1));
}

// ---------------------------------------------------------------------------
// bf16 hi/lo split kernel (vectorized float4)
// ---------------------------------------------------------------------------
__global__ void split_bf16(const float4* __restrict__ in,
                           __nv_bfloat162* __restrict__ hi,
                           __nv_bfloat162* __restrict__ lo, int n4) {
    int i = blockIdx.x * blockDim.x + threadIdx.x;
    if (i >= n4) return;
    float4 v = in[i];
    __nv_bfloat16 h0 = __float2bfloat16_rn(v.x);
    __nv_bfloat16 h1 = __float2bfloat16_rn(v.y);
    __nv_bfloat16 h2 = __float2bfloat16_rn(v.z);
    __nv_bfloat16 h3 = __float2bfloat16_rn(v.w);
    __nv_bfloat16 l0 = __float2bfloat16_rn(v.x - __bfloat162float(h0));
    __nv_bfloat16 l1 = __float2bfloat16_rn(v.y - __bfloat162float(h1));
    __nv_bfloat16 l2 = __float2bfloat16_rn(v.z - __bfloat162float(h2));
    __nv_bfloat16 l3 = __float2bfloat16_rn(v.w - __bfloat162float(h3));
    hi[2 * i]     = __nv_bfloat162(h0, h1);
    hi[2 * i + 1] = __nv_bfloat162(h2, h3);
    lo[2 * i]     = __nv_bfloat162(l0, l1);
    lo[2 * i + 1] = __nv_bfloat162(l2, l3);
}

// ---------------------------------------------------------------------------
// mma.sync bf16x3 GEMM: C[m,n] = sum_k A[m,k]*B[n,k] (+bias[n])
// 128x128 CTA tile, 8 warps (warp tile 32x64), BK=32.
// smem tiles [128][40] bf16 (stride-40 padding: ldmatrix conflict-free).
// 3 passes: Ahi*Bhi + Ahi*Blo + Alo*Bhi.
// ---------------------------------------------------------------------------
#define SA_STRIDE 40
#define TILE_BYTES (128 * SA_STRIDE * 2)   // 10240
#define GEMM_SMEM (4 * TILE_BYTES)         // 40960

template <bool HAS_BIAS>
__global__ __launch_bounds__(256)
void gemm_mma(const __nv_bfloat16* __restrict__ Ahi, const __nv_bfloat16* __restrict__ Alo,
              const __nv_bfloat16* __restrict__ Bhi, const __nv_bfloat16* __restrict__ Blo,
              const float* __restrict__ bias, float* __restrict__ C, int N, int K) {
    extern __shared__ char smem[];
    const uint32_t sb = smem_u32(smem);
    const uint32_t SA_HI = sb;
    const uint32_t SA_LO = sb + TILE_BYTES;
    const uint32_t SB_HI = sb + 2 * TILE_BYTES;
    const uint32_t SB_LO = sb + 3 * TILE_BYTES;

    const int tid  = threadIdx.x;
    const int wid  = tid >> 5;
    const int lane = tid & 31;
    const int n0 = blockIdx.x * 128;
    const int m0 = blockIdx.y * 128;
    const int wm = (wid & 3) * 32;   // warp m-offset within CTA tile
    const int wn = (wid >> 2) * 64;  // warp n-offset

    const int trow  = lane & 7;
    const int tquad = lane >> 3;
    // ldmatrix per-lane offsets (elements), before *2 bytes
    const int a_row_off = (tquad & 1) * 8 + trow;    // within 16-row m-tile
    const int a_col_off = (tquad >> 1) * 8;          // within 16-col k-step
    const int b_row_off = (tquad >> 1) * 8 + trow;   // within 16-row n-pair
    const int b_col_off = (tquad & 1) * 8;

    float acc[2][8][4];
#pragma unroll
    for (int mt = 0; mt < 2; mt++)
#pragma unroll
        for (int nt = 0; nt < 8; nt++)
#pragma unroll
            for (int j = 0; j < 4; j++) acc[mt][nt][j] = 0.0f;

    for (int k0 = 0; k0 < K; k0 += 32) {
        // ---- load 4 tiles: 128 rows x 32 bf16 each (2 uint4 per thread) ----
#pragma unroll
        for (int i = 0; i < 2; i++) {
            int idx = tid * 2 + i;           // 0..511
            int row = idx >> 2, q = idx & 3; // q: 8-elem quad
            uint32_t soff = (uint32_t)(row * SA_STRIDE + q * 8) * 2;
            size_t ga = (size_t)(m0 + row) * K + k0 + q * 8;
            size_t gb = (size_t)(n0 + row) * K + k0 + q * 8;
            *(uint4*)(smem + (SA_HI - sb) + soff) = *(const uint4*)(Ahi + ga);
            *(uint4*)(smem + (SA_LO - sb) + soff) = *(const uint4*)(Alo + ga);
            *(uint4*)(smem + (SB_HI - sb) + soff) = *(const uint4*)(Bhi + gb);
            *(uint4*)(smem + (SB_LO - sb) + soff) = *(const uint4*)(Blo + gb);
        }
        __syncthreads();

        // ---- 3 precision passes x 2 k-steps ----
#pragma unroll
        for (int pass = 0; pass < 3; pass++) {
            const uint32_t abase = (pass == 2) ? SA_LO : SA_HI;
            const uint32_t bbase = (pass == 1) ? SB_LO : SB_HI;
#pragma unroll
            for (int ks = 0; ks < 2; ks++) {
                const int kk = ks * 16;
                uint32_t a[2][4];
#pragma unroll
                for (int mt = 0; mt < 2; mt++) {
                    uint32_t addr = abase +
                        (uint32_t)((wm + mt * 16 + a_row_off) * SA_STRIDE +
                                   kk + a_col_off) * 2;
                    ldsm_x4(addr, a[mt]);
                }
                uint32_t b[4][4];   // 4 x4 loads; each covers two 8-wide n-tiles
#pragma unroll
                for (int np = 0; np < 4; np++) {
                    uint32_t addr = bbase +
                        (uint32_t)((wn + np * 16 + b_row_off) * SA_STRIDE +
                                   kk + b_col_off) * 2;
                    ldsm_x4(addr, b[np]);
                }
#pragma unroll
                for (int mt = 0; mt < 2; mt++)
#pragma unroll
                    for (int np = 0; np < 4; np++) {
                        mma16816(acc[mt][2 * np],     a[mt], b[np][0], b[np][1]);
                        mma16816(acc[mt][2 * np + 1], a[mt], b[np][2], b[np][3]);
                    }
            }
        }
        __syncthreads();
    }

    // ---- epilogue: write fragments (float2 stores) ----
    const int g = lane >> 2;
    const int t2 = (lane & 3) * 2;
#pragma unroll
    for (int mt = 0; mt < 2; mt++) {
        int mrow0 = m0 + wm + mt * 16 + g;
#pragma unroll
        for (int nt = 0; nt < 8; nt++) {
            int n = n0 + wn + nt * 8 + t2;
            float b0 = 0.f, b1 = 0.f;
            if (HAS_BIAS) { b0 = bias[n]; b1 = bias[n + 1]; }
            float2 v0 = make_float2(acc[mt][nt][0] + b0, acc[mt][nt][1] + b1);
            float2 v1 = make_float2(acc[mt][nt][2] + b0, acc[mt][nt][3] + b1);
            *(float2*)(C + (size_t)mrow0 * N + n)       = v0;
            *(float2*)(C + (size_t)(mrow0 + 8) * N + n) = v1;
        }
    }
}

// ---------------------------------------------------------------------------
// Causal flash attention, fp32 SIMT (unchanged; passed R1).
// ---------------------------------------------------------------------------
#define ATTN_SMEM (4 * 64 * 68 * 4)

__global__ __launch_bounds__(256)
void attn_kernel(const float* __restrict__ qkv, float* __restrict__ att) {
    extern __shared__ float sm[];
    float* QsT = sm;                // [d][r]  stride 68
    float* KsT = sm + 64 * 68;      // [d][c]
    float* Vs  = sm + 2 * 64 * 68;  // [n][d]
    float* PsT = sm + 3 * 64 * 68;  // [n][r]

    const int t  = threadIdx.x;
    const int tx = t & 15;
    const int ty = t >> 4;
    const int it = blockIdx.x;
    const int h  = blockIdx.y;
    const int b  = blockIdx.z;
    const size_t base = (size_t)b * SEQ * F3 + (size_t)h * 192;

#pragma unroll
    for (int i = 0; i < 4; i++) {
        int idx = t + 256 * i;
        int r = idx >> 4;
        int q = idx & 15;
        float4 v = *(const float4*)(qkv + base + (size_t)(it * 64 + r) * F3 + 4 * q);
        QsT[(4 * q + 0) * 68 + r] = v.x;
        QsT[(4 * q + 1) * 68 + r] = v.y;
        QsT[(4 * q + 2) * 68 + r] = v.z;
        QsT[(4 * q + 3) * 68 + r] = v.w;
    }

    float m_i[4], l_i[4], acc[4][4];
#pragma unroll
    for (int i = 0; i < 4; i++) {
        m_i[i] = -1e30f;
        l_i[i] = 0.0f;
#pragma unroll
        for (int j = 0; j < 4; j++) acc[i][j] = 0.0f;
    }

    for (int jt = 0; jt <= it; jt++) {
        __syncthreads();
#pragma unroll
        for (int i = 0; i < 4; i++) {
            int idx = t + 256 * i;
            int r = idx >> 4;
            int q = idx & 15;
            const float* kp = qkv + base + (size_t)(jt * 64 + r) * F3 + 64 + 4 * q;
            float4 kv = *(const float4*)kp;
            KsT[(4 * q + 0) * 68 + r] = kv.x;
            KsT[(4 * q + 1) * 68 + r] = kv.y;
            KsT[(4 * q + 2) * 68 + r] = kv.z;
            KsT[(4 * q + 3) * 68 + r] = kv.w;
            float4 vv = *(const float4*)(kp + 64);
            *(float4*)&Vs[r * 68 + 4 * q] = vv;
        }
        __syncthreads();

        float s[4][4];
#pragma unroll
        for (int ii = 0; ii < 4; ii++)
#pragma unroll
            for (int jj = 0; jj < 4; jj++) s[ii][jj] = 0.0f;

#pragma unroll 8
        for (int d = 0; d < 64; d++) {
            float4 q4 = *(const float4*)&QsT[d * 68 + 4 * ty];
            float4 k4 = *(const float4*)&KsT[d * 68 + 4 * tx];
            float qa[4] = {q4.x, q4.y, q4.z, q4.w};
            float ka[4] = {k4.x, k4.y, k4.z, k4.w};
#pragma unroll
            for (int ii = 0; ii < 4; ii++)
#pragma unroll
                for (int jj = 0; jj < 4; jj++) s[ii][jj] += qa[ii] * ka[jj];
        }

        const float scale = 0.125f;
#pragma unroll
        for (int ii = 0; ii < 4; ii++)
#pragma unroll
            for (int jj = 0; jj < 4; jj++) {
                s[ii][jj] *= scale;
                if (jt == it && (4 * tx + jj) > (4 * ty + ii)) s[ii][jj] = -1e30f;
            }

        float mloc[4];
#pragma unroll
        for (int ii = 0; ii < 4; ii++)
            mloc[ii] = fmaxf(fmaxf(s[ii][0], s[ii][1]), fmaxf(s[ii][2], s[ii][3]));
#pragma unroll
        for (int off = 8; off >= 1; off >>= 1)
#pragma unroll
            for (int ii = 0; ii < 4; ii++)
                mloc[ii] = fmaxf(mloc[ii], __shfl_xor_sync(0xffffffffu, mloc[ii], off));

        float mnew[4], alpha[4], rsum[4];
#pragma unroll
        for (int ii = 0; ii < 4; ii++) {
            mnew[ii]  = fmaxf(m_i[ii], mloc[ii]);
            alpha[ii] = __expf(m_i[ii] - mnew[ii]);
        }

        float p[4][4];
#pragma unroll
        for (int ii = 0; ii < 4; ii++) {
            float rs = 0.0f;
#pragma unroll
            for (int jj = 0; jj < 4; jj++) {
                float pv = __expf(s[ii][jj] - mnew[ii]);
                p[ii][jj] = pv;
                rs += pv;
            }
            rsum[ii] = rs;
        }
#pragma unroll
        for (int off = 8; off >= 1; off >>= 1)
#pragma unroll
            for (int ii = 0; ii < 4; ii++)
                rsum[ii] += __shfl_xor_sync(0xffffffffu, rsum[ii], off);

#pragma unroll
        for (int ii = 0; ii < 4; ii++) {
            l_i[ii] = l_i[ii] * alpha[ii] + rsum[ii];
            m_i[ii] = mnew[ii];
#pragma unroll
            for (int jj = 0; jj < 4; jj++) acc[ii][jj] *= alpha[ii];
        }

#pragma unroll
        for (int jj = 0; jj < 4; jj++) {
            float4 pc = make_float4(p[0][jj], p[1][jj], p[2][jj], p[3][jj]);
            *(float4*)&PsT[(4 * tx + jj) * 68 + 4 * ty] = pc;
        }
        __syncthreads();

#pragma unroll 8
        for (int n = 0; n < 64; n++) {
            float4 p4 = *(const float4*)&PsT[n * 68 + 4 * ty];
            float4 v4 = *(const float4*)&Vs[n * 68 + 4 * tx];
            float pa[4] = {p4.x, p4.y, p4.z, p4.w};
            float va[4] = {v4.x, v4.y, v4.z, v4.w};
#pragma unroll
            for (int ii = 0; ii < 4; ii++)
#pragma unroll
                for (int jj = 0; jj < 4; jj++) acc[ii][jj] += pa[ii] * va[jj];
        }
    }

#pragma unroll
    for (int ii = 0; ii < 4; ii++) {
        int grow = it * 64 + 4 * ty + ii;
        float inv_l = 1.0f / l_i[ii];
        float4 o = make_float4(acc[ii][0] * inv_l, acc[ii][1] * inv_l,
                               acc[ii][2] * inv_l, acc[ii][3] * inv_l);
        *(float4*)(att + ((size_t)b * SEQ + grow) * EMB + h * 64 + 4 * tx) = o;
    }
}

// ---------------------------------------------------------------------------
// Launch
// ---------------------------------------------------------------------------
extern "C" void kernel_launch(void* const* d_in, const int* in_sizes, int n_in,
                              void* d_out, int out_size) {
    const float* x      = (const float*)d_in[0];
    const float* w_qkv  = (const float*)d_in[1];
    const float* w_out  = (const float*)d_in[2];
    const float* b_out  = (const float*)d_in[3];
    float* out = (float*)d_out;

    float *qkv, *att;
    __nv_bfloat16 *x_hi, *x_lo, *wq_hi, *wq_lo, *wo_hi, *wo_lo, *a_hi, *a_lo;
    cudaGetSymbolAddress((void**)&qkv,   g_qkv);
    cudaGetSymbolAddress((void**)&att,   g_att);
    cudaGetSymbolAddress((void**)&x_hi,  g_x_hi);
    cudaGetSymbolAddress((void**)&x_lo,  g_x_lo);
    cudaGetSymbolAddress((void**)&wq_hi, g_wqkv_hi);
    cudaGetSymbolAddress((void**)&wq_lo, g_wqkv_lo);
    cudaGetSymbolAddress((void**)&wo_hi, g_wout_hi);
    cudaGetSymbolAddress((void**)&wo_lo, g_wout_lo);
    cudaGetSymbolAddress((void**)&a_hi,  g_att_hi);
    cudaGetSymbolAddress((void**)&a_lo,  g_att_lo);

    cudaFuncSetAttribute(attn_kernel,
                         cudaFuncAttributeMaxDynamicSharedMemorySize, ATTN_SMEM);
    cudaFuncSetAttribute(gemm_mma<false>,
                         cudaFuncAttributeMaxDynamicSharedMemorySize, GEMM_SMEM);
    cudaFuncSetAttribute(gemm_mma<true>,
                         cudaFuncAttributeMaxDynamicSharedMemorySize, GEMM_SMEM);

    // 0) bf16 hi/lo splits of x and weights
    {
        int n4 = ROWS * EMB / 4;
        split_bf16<<<(n4 + 255) / 256, 256>>>((const float4*)x,
            (__nv_bfloat162*)x_hi, (__nv_bfloat162*)x_lo, n4);
        n4 = F3 * EMB / 4;
        split_bf16<<<(n4 + 255) / 256, 256>>>((const float4*)w_qkv,
            (__nv_bfloat162*)wq_hi, (__nv_bfloat162*)wq_lo, n4);
        n4 = EMB * EMB / 4;
        split_bf16<<<(n4 + 255) / 256, 256>>>((const float4*)w_out,
            (__nv_bfloat162*)wo_hi, (__nv_bfloat162*)wo_lo, n4);
    }

    // 1) QKV projection on tensor cores (mma.sync bf16x3): [4096,3072]
    gemm_mma<false><<<dim3(F3 / 128, ROWS / 128), 256, GEMM_SMEM>>>(
        x_hi, x_lo, wq_hi, wq_lo, nullptr, qkv, F3, EMB);

    // 2) Causal flash attention (fp32 SIMT)
    attn_kernel<<<dim3(SEQ / 64, NH, BS), 256, ATTN_SMEM>>>(qkv, att);

    // 3) Split attention output, then out projection + bias on tensor cores
    {
        int n4 = ROWS * EMB / 4;
        split_bf16<<<(n4 + 255) / 256, 256>>>((const float4*)att,
            (__nv_bfloat162*)a_hi, (__nv_bfloat162*)a_lo, n4);
    }
    gemm_mma<true><<<dim3(EMB / 128, ROWS / 128), 256, GEMM_SMEM>>>(
        a_hi, a_lo, wo_hi, wo_lo, b_out, out, EMB, EMB);
}

// round 4
// speedup vs baseline: 2.0740x; 1.5404x over previous
#include <cuda_runtime.h>
#include <cuda_bf16.h>
#include <cstdint>
#include <math.h>

// Problem constants (fixed shapes)
#define BS   2
#define SEQ  2048
#define EMB  1024
#define NH   16
#define HD   64
#define F3   3072   // 3*EMB
#define ROWS (BS * SEQ)   // 4096

// ---------------------------------------------------------------------------
// Scratch (device globals: allocation-free rule)
// ---------------------------------------------------------------------------
__device__ __nv_bfloat16 g_x_hi[ROWS * EMB];
__device__ __nv_bfloat16 g_x_lo[ROWS * EMB];
__device__ __nv_bfloat16 g_wqkv_hi[F3 * EMB];
__device__ __nv_bfloat16 g_wqkv_lo[F3 * EMB];
__device__ __nv_bfloat16 g_wout_hi[EMB * EMB];
__device__ __nv_bfloat16 g_wout_lo[EMB * EMB];
__device__ __nv_bfloat16 g_qkv_hi[ROWS * F3];
__device__ __nv_bfloat16 g_qkv_lo[ROWS * F3];
__device__ __nv_bfloat16 g_att_hi[ROWS * EMB];
__device__ __nv_bfloat16 g_att_lo[ROWS * EMB];

// ---------------------------------------------------------------------------
// helpers
// ---------------------------------------------------------------------------
__device__ __forceinline__ uint32_t smem_u32(const void* p) {
    uint32_t a;
    asm("{ .reg .u64 t; cvta.to.shared.u64 t, %1; cvt.u32.u64 %0, t; }" : "=r"(a) : "l"(p));
    return a;
}
__device__ __forceinline__ void ldsm_x4(uint32_t addr, uint32_t r[4]) {
    asm volatile("ldmatrix.sync.aligned.m8n8.x4.shared.b16 {%0,%1,%2,%3}, [%4];"
                 : "=r"(r[0]), "=r"(r[1]), "=r"(r[2]), "=r"(r[3]) : "r"(addr));
}
__device__ __forceinline__ void ldsm_x4_t(uint32_t addr, uint32_t r[4]) {
    asm volatile("ldmatrix.sync.aligned.m8n8.x4.trans.shared.b16 {%0,%1,%2,%3}, [%4];"
                 : "=r"(r[0]), "=r"(r[1]), "=r"(r[2]), "=r"(r[3]) : "r"(addr));
}
__device__ __forceinline__ void mma16816(float c[4], const uint32_t a[4],
                                         const uint32_t b0, const uint32_t b1) {
    asm volatile(
        "mma.sync.aligned.m16n8k16.row.col.f32.bf16.bf16.f32 "
        "{%0,%1,%2,%3}, {%4,%5,%6,%7}, {%8,%9}, {%0,%1,%2,%3};"
        : "+f"(c[0]), "+f"(c[1]), "+f"(c[2]), "+f"(c[3])
        : "r"(a[0]), "r"(a[1]), "r"(a[2]), "r"(a[3]), "r"(b0), "r"(b1));
}
__device__ __forceinline__ uint32_t pack_bf16(float lo, float hi) {
    uint32_t r;
    asm("cvt.rn.bf16x2.f32 %0, %1, %2;" : "=r"(r) : "f"(hi), "f"(lo));
    return r;
}
__device__ __forceinline__ float ex2(float x) {
    float r;
    asm("ex2.approx.ftz.f32 %0, %1;" : "=f"(r) : "f"(x));
    return r;
}

// ---------------------------------------------------------------------------
// bf16 hi/lo split (float4 vectorized)
// ---------------------------------------------------------------------------
__global__ void split_bf16(const float4* __restrict__ in,
                           __nv_bfloat162* __restrict__ hi,
                           __nv_bfloat162* __restrict__ lo, int n4) {
    int i = blockIdx.x * blockDim.x + threadIdx.x;
    if (i >= n4) return;
    float4 v = in[i];
    __nv_bfloat16 h0 = __float2bfloat16_rn(v.x);
    __nv_bfloat16 h1 = __float2bfloat16_rn(v.y);
    __nv_bfloat16 h2 = __float2bfloat16_rn(v.z);
    __nv_bfloat16 h3 = __float2bfloat16_rn(v.w);
    __nv_bfloat16 l0 = __float2bfloat16_rn(v.x - __bfloat162float(h0));
    __nv_bfloat16 l1 = __float2bfloat16_rn(v.y - __bfloat162float(h1));
    __nv_bfloat16 l2 = __float2bfloat16_rn(v.z - __bfloat162float(h2));
    __nv_bfloat16 l3 = __float2bfloat16_rn(v.w - __bfloat162float(h3));
    hi[2 * i]     = __nv_bfloat162(h0, h1);
    hi[2 * i + 1] = __nv_bfloat162(h2, h3);
    lo[2 * i]     = __nv_bfloat162(l0, l1);
    lo[2 * i + 1] = __nv_bfloat162(l2, l3);
}

// ---------------------------------------------------------------------------
// mma.sync bf16x3 GEMM. SPLIT_OUT: write bf16 hi/lo pair instead of fp32.
// 128x128 CTA tile, 8 warps (warp tile 32x64), BK=32.
// ---------------------------------------------------------------------------
#define SA_STRIDE 40
#define TILE_BYTES (128 * SA_STRIDE * 2)   // 10240
#define GEMM_SMEM (4 * TILE_BYTES)         // 40960

template <bool HAS_BIAS, bool SPLIT_OUT>
__global__ __launch_bounds__(256)
void gemm_mma(const __nv_bfloat16* __restrict__ Ahi, const __nv_bfloat16* __restrict__ Alo,
              const __nv_bfloat16* __restrict__ Bhi, const __nv_bfloat16* __restrict__ Blo,
              const float* __restrict__ bias, float* __restrict__ C,
              __nv_bfloat16* __restrict__ Chi, __nv_bfloat16* __restrict__ Clo,
              int N, int K) {
    extern __shared__ char smem[];
    const uint32_t sb = smem_u32(smem);
    const uint32_t SA_HI = sb;
    const uint32_t SA_LO = sb + TILE_BYTES;
    const uint32_t SB_HI = sb + 2 * TILE_BYTES;
    const uint32_t SB_LO = sb + 3 * TILE_BYTES;

    const int tid  = threadIdx.x;
    const int wid  = tid >> 5;
    const int lane = tid & 31;
    const int n0 = blockIdx.x * 128;
    const int m0 = blockIdx.y * 128;
    const int wm = (wid & 3) * 32;
    const int wn = (wid >> 2) * 64;

    const int trow  = lane & 7;
    const int tquad = lane >> 3;
    const int a_row_off = (tquad & 1) * 8 + trow;
    const int a_col_off = (tquad >> 1) * 8;
    const int b_row_off = (tquad >> 1) * 8 + trow;
    const int b_col_off = (tquad & 1) * 8;

    float acc[2][8][4];
#pragma unroll
    for (int mt = 0; mt < 2; mt++)
#pragma unroll
        for (int nt = 0; nt < 8; nt++)
#pragma unroll
            for (int j = 0; j < 4; j++) acc[mt][nt][j] = 0.0f;

    for (int k0 = 0; k0 < K; k0 += 32) {
#pragma unroll
        for (int i = 0; i < 2; i++) {
            int idx = tid * 2 + i;
            int row = idx >> 2, q = idx & 3;
            uint32_t soff = (uint32_t)(row * SA_STRIDE + q * 8) * 2;
            size_t ga = (size_t)(m0 + row) * K + k0 + q * 8;
            size_t gb = (size_t)(n0 + row) * K + k0 + q * 8;
            *(uint4*)(smem + soff)                  = *(const uint4*)(Ahi + ga);
            *(uint4*)(smem + TILE_BYTES + soff)     = *(const uint4*)(Alo + ga);
            *(uint4*)(smem + 2 * TILE_BYTES + soff) = *(const uint4*)(Bhi + gb);
            *(uint4*)(smem + 3 * TILE_BYTES + soff) = *(const uint4*)(Blo + gb);
        }
        __syncthreads();

#pragma unroll
        for (int pass = 0; pass < 3; pass++) {
            const uint32_t abase = (pass == 2) ? SA_LO : SA_HI;
            const uint32_t bbase = (pass == 1) ? SB_LO : SB_HI;
#pragma unroll
            for (int ks = 0; ks < 2; ks++) {
                const int kk = ks * 16;
                uint32_t a[2][4];
#pragma unroll
                for (int mt = 0; mt < 2; mt++) {
                    uint32_t addr = abase +
                        (uint32_t)((wm + mt * 16 + a_row_off) * SA_STRIDE +
                                   kk + a_col_off) * 2;
                    ldsm_x4(addr, a[mt]);
                }
                uint32_t b[4][4];
#pragma unroll
                for (int np = 0; np < 4; np++) {
                    uint32_t addr = bbase +
                        (uint32_t)((wn + np * 16 + b_row_off) * SA_STRIDE +
                                   kk + b_col_off) * 2;
                    ldsm_x4(addr, b[np]);
                }
#pragma unroll
                for (int mt = 0; mt < 2; mt++)
#pragma unroll
                    for (int np = 0; np < 4; np++) {
                        mma16816(acc[mt][2 * np],     a[mt], b[np][0], b[np][1]);
                        mma16816(acc[mt][2 * np + 1], a[mt], b[np][2], b[np][3]);
                    }
            }
        }
        __syncthreads();
    }

    const int g  = lane >> 2;
    const int t2 = (lane & 3) * 2;
#pragma unroll
    for (int mt = 0; mt < 2; mt++) {
        int mrow0 = m0 + wm + mt * 16 + g;
#pragma unroll
        for (int nt = 0; nt < 8; nt++) {
            int n = n0 + wn + nt * 8 + t2;
            float b0 = 0.f, b1 = 0.f;
            if (HAS_BIAS) { b0 = bias[n]; b1 = bias[n + 1]; }
            float v00 = acc[mt][nt][0] + b0, v01 = acc[mt][nt][1] + b1;
            float v10 = acc[mt][nt][2] + b0, v11 = acc[mt][nt][3] + b1;
            if (SPLIT_OUT) {
                size_t i0 = (size_t)mrow0 * N + n;
                size_t i1 = (size_t)(mrow0 + 8) * N + n;
                float h00 = __bfloat162float(__float2bfloat16_rn(v00));
                float h01 = __bfloat162float(__float2bfloat16_rn(v01));
                float h10 = __bfloat162float(__float2bfloat16_rn(v10));
                float h11 = __bfloat162float(__float2bfloat16_rn(v11));
                *(uint32_t*)(Chi + i0) = pack_bf16(h00, h01);
                *(uint32_t*)(Clo + i0) = pack_bf16(v00 - h00, v01 - h01);
                *(uint32_t*)(Chi + i1) = pack_bf16(h10, h11);
                *(uint32_t*)(Clo + i1) = pack_bf16(v10 - h10, v11 - h11);
            } else {
                *(float2*)(C + (size_t)mrow0 * N + n)       = make_float2(v00, v01);
                *(float2*)(C + (size_t)(mrow0 + 8) * N + n) = make_float2(v10, v11);
            }
        }
    }
}

// ---------------------------------------------------------------------------
// Tensor-core causal flash attention (bf16x3), BM=128, BN=64, HD=64, 8 warps.
// qkv_hi/lo layout: [b*SEQ + s][h*192 + c]; c: q 0-63, k 64-127, v 128-191.
// Output: att hi/lo [b*SEQ + s][h*64 + d].
// ---------------------------------------------------------------------------
#define AT_STRIDE 72
#define AT_TILE (64 * AT_STRIDE * 2)   // 9216 bytes
#define ATTN_SMEM (4 * AT_TILE)        // 36864: KH, KL, VH, VL

#define SCALE2 0.1803368801111244f     // 0.125 * log2(e)

__global__ __launch_bounds__(256)
void attn_mma(const __nv_bfloat16* __restrict__ qkv_hi,
              const __nv_bfloat16* __restrict__ qkv_lo,
              __nv_bfloat16* __restrict__ att_hi,
              __nv_bfloat16* __restrict__ att_lo) {
    extern __shared__ char smem[];
    const uint32_t sb = smem_u32(smem);
    const uint32_t KH = sb, KL = sb + AT_TILE, VH = sb + 2 * AT_TILE, VL = sb + 3 * AT_TILE;

    const int tid  = threadIdx.x;
    const int wid  = tid >> 5;
    const int lane = tid & 31;
    const int it = blockIdx.x;      // 128-row query tile
    const int h  = blockIdx.y;
    const int b  = blockIdx.z;
    const size_t hbase = (size_t)b * SEQ * F3 + (size_t)h * 192;

    // ---- Stage Q (128x64 hi & lo) through the 4 smem buffers ----
#pragma unroll
    for (int i = 0; i < 2; i++) {
        int idx = tid * 2 + i;        // 0..511
        int row = idx >> 3, q = idx & 7;
        uint32_t soff = (uint32_t)(row * AT_STRIDE + q * 8) * 2;
        size_t glo = hbase + (size_t)(it * 128 + row) * F3 + q * 8;
        size_t ghi = hbase + (size_t)(it * 128 + 64 + row) * F3 + q * 8;
        *(uint4*)(smem + soff)               = *(const uint4*)(qkv_hi + glo);   // KH
        *(uint4*)(smem + AT_TILE + soff)     = *(const uint4*)(qkv_lo + glo);   // KL
        *(uint4*)(smem + 2 * AT_TILE + soff) = *(const uint4*)(qkv_hi + ghi);   // VH
        *(uint4*)(smem + 3 * AT_TILE + soff) = *(const uint4*)(qkv_lo + ghi);   // VL
    }
    __syncthreads();

    // Q fragments (register resident): warp w owns rows 16*(w&3) + 64*(w>>2)
    uint32_t qh[4][4], ql[4][4];
    {
        uint32_t hb = (wid < 4) ? KH : VH;
        uint32_t lb = (wid < 4) ? KL : VL;
        uint32_t qoff = (uint32_t)((16 * (wid & 3) + (lane & 15)) * AT_STRIDE +
                                   (lane >> 4) * 8) * 2;
#pragma unroll
        for (int ks = 0; ks < 4; ks++) {
            ldsm_x4(hb + qoff + ks * 32, qh[ks]);
            ldsm_x4(lb + qoff + ks * 32, ql[ks]);
        }
    }

    float m2[2] = {-1e30f, -1e30f}, l[2] = {0.f, 0.f};
    float o[8][4];
#pragma unroll
    for (int dt = 0; dt < 8; dt++)
#pragma unroll
        for (int j = 0; j < 4; j++) o[dt][j] = 0.0f;

    const int rbase = 128 * it + 16 * (wid & 3) + 64 * (wid >> 2);
    const int g  = lane >> 2;
    const int t2 = (lane & 3) * 2;
    // precomputed ldmatrix lane offsets (bytes)
    const uint32_t koff = (uint32_t)(((lane >> 4) * 8 + (lane & 7)) * AT_STRIDE +
                                     ((lane >> 3) & 1) * 8) * 2;
    const uint32_t voff = (uint32_t)((lane & 15) * AT_STRIDE + (lane >> 4) * 8) * 2;

    const int jt_max = 2 * it + 2;
    for (int jt = 0; jt < jt_max; jt++) {
        __syncthreads();   // previous iter's (and Q-stage) smem reads done
#pragma unroll
        for (int i = 0; i < 2; i++) {
            int idx = tid * 2 + i;
            int row = idx >> 3, q = idx & 7;
            uint32_t soff = (uint32_t)(row * AT_STRIDE + q * 8) * 2;
            size_t gr = hbase + (size_t)(jt * 64 + row) * F3 + q * 8;
            *(uint4*)(smem + soff)               = *(const uint4*)(qkv_hi + gr + 64);    // K hi
            *(uint4*)(smem + AT_TILE + soff)     = *(const uint4*)(qkv_lo + gr + 64);    // K lo
            *(uint4*)(smem + 2 * AT_TILE + soff) = *(const uint4*)(qkv_hi + gr + 128);   // V hi
            *(uint4*)(smem + 3 * AT_TILE + soff) = *(const uint4*)(qkv_lo + gr + 128);   // V lo
        }
        __syncthreads();

        // ---- S = Q K^T (3 passes) ----
        float s[8][4];
#pragma unroll
        for (int nt = 0; nt < 8; nt++)
#pragma unroll
            for (int j = 0; j < 4; j++) s[nt][j] = 0.0f;

#pragma unroll
        for (int pass = 0; pass < 3; pass++) {
            const uint32_t kb = (pass == 1) ? KL : KH;
#pragma unroll
            for (int ks = 0; ks < 4; ks++) {
                const uint32_t* A = (pass == 2) ? ql[ks] : qh[ks];
#pragma unroll
                for (int np = 0; np < 4; np++) {
                    uint32_t bb[4];
                    ldsm_x4(kb + koff + (uint32_t)(np * 16 * AT_STRIDE + ks * 16) * 2, bb);
                    mma16816(s[2 * np],     A, bb[0], bb[1]);
                    mma16816(s[2 * np + 1], A, bb[2], bb[3]);
                }
            }
        }

        // ---- scale (+ causal mask on diagonal tiles) ----
        const bool diag = (jt >= 2 * it);
#pragma unroll
        for (int nt = 0; nt < 8; nt++)
#pragma unroll
            for (int j = 0; j < 4; j++) {
                float t = s[nt][j] * SCALE2;
                if (diag) {
                    int col = jt * 64 + nt * 8 + t2 + (j & 1);
                    int row = rbase + g + 8 * (j >> 1);
                    if (col > row) t = -1e30f;
                }
                s[nt][j] = t;
            }

        // ---- online softmax ----
        float rmax[2] = {-1e30f, -1e30f};
#pragma unroll
        for (int nt = 0; nt < 8; nt++) {
            rmax[0] = fmaxf(rmax[0], fmaxf(s[nt][0], s[nt][1]));
            rmax[1] = fmaxf(rmax[1], fmaxf(s[nt][2], s[nt][3]));
        }
#pragma unroll
        for (int off = 1; off <= 2; off <<= 1) {
            rmax[0] = fmaxf(rmax[0], __shfl_xor_sync(0xffffffffu, rmax[0], off));
            rmax[1] = fmaxf(rmax[1], __shfl_xor_sync(0xffffffffu, rmax[1], off));
        }
        float alpha[2], rsum[2];
#pragma unroll
        for (int r = 0; r < 2; r++) {
            float mnew = fmaxf(m2[r], rmax[r]);
            alpha[r] = ex2(m2[r] - mnew);
            m2[r] = mnew;
            rsum[r] = 0.f;
        }
#pragma unroll
        for (int nt = 0; nt < 8; nt++) {
            s[nt][0] = ex2(s[nt][0] - m2[0]);
            s[nt][1] = ex2(s[nt][1] - m2[0]);
            s[nt][2] = ex2(s[nt][2] - m2[1]);
            s[nt][3] = ex2(s[nt][3] - m2[1]);
            rsum[0] += s[nt][0] + s[nt][1];
            rsum[1] += s[nt][2] + s[nt][3];
        }
#pragma unroll
        for (int off = 1; off <= 2; off <<= 1) {
            rsum[0] += __shfl_xor_sync(0xffffffffu, rsum[0], off);
            rsum[1] += __shfl_xor_sync(0xffffffffu, rsum[1], off);
        }
#pragma unroll
        for (int r = 0; r < 2; r++) l[r] = l[r] * alpha[r] + rsum[r];
#pragma unroll
        for (int dt = 0; dt < 8; dt++) {
            o[dt][0] *= alpha[0];
            o[dt][1] *= alpha[0];
            o[dt][2] *= alpha[1];
            o[dt][3] *= alpha[1];
        }

        // ---- pack P into A-fragments (hi + lo) ----
        uint32_t ph[4][4], pl[4][4];
#pragma unroll
        for (int ks = 0; ks < 4; ks++) {
#pragma unroll
            for (int half = 0; half < 2; half++) {       // ntile 2ks, 2ks+1
                int nt = 2 * ks + half;
                float p0 = s[nt][0], p1 = s[nt][1], p2 = s[nt][2], p3 = s[nt][3];
                float h0 = __bfloat162float(__float2bfloat16_rn(p0));
                float h1 = __bfloat162float(__float2bfloat16_rn(p1));
                float h2 = __bfloat162float(__float2bfloat16_rn(p2));
                float h3 = __bfloat162float(__float2bfloat16_rn(p3));
                ph[ks][2 * half]     = pack_bf16(h0, h1);
                ph[ks][2 * half + 1] = pack_bf16(h2, h3);
                pl[ks][2 * half]     = pack_bf16(p0 - h0, p1 - h1);
                pl[ks][2 * half + 1] = pack_bf16(p2 - h2, p3 - h3);
            }
        }

        // ---- O += P V (3 passes; V via ldmatrix.trans) ----
#pragma unroll
        for (int pass = 0; pass < 3; pass++) {
            const uint32_t vb = (pass == 1) ? VL : VH;
#pragma unroll
            for (int ks = 0; ks < 4; ks++) {
                const uint32_t* A = (pass == 2) ? pl[ks] : ph[ks];
#pragma unroll
                for (int np = 0; np < 4; np++) {
                    uint32_t bv[4];
                    ldsm_x4_t(vb + voff + (uint32_t)(ks * 16 * AT_STRIDE + np * 16) * 2, bv);
                    mma16816(o[2 * np],     A, bv[0], bv[1]);
                    mma16816(o[2 * np + 1], A, bv[2], bv[3]);
                }
            }
        }
    }

    // ---- epilogue: O/l -> att hi/lo ----
    float inv0 = 1.0f / l[0], inv1 = 1.0f / l[1];
#pragma unroll
    for (int dt = 0; dt < 8; dt++) {
        int col = h * 64 + dt * 8 + t2;
        size_t i0 = ((size_t)b * SEQ + rbase + g) * EMB + col;
        size_t i1 = ((size_t)b * SEQ + rbase + g + 8) * EMB + col;
        float v00 = o[dt][0] * inv0, v01 = o[dt][1] * inv0;
        float v10 = o[dt][2] * inv1, v11 = o[dt][3] * inv1;
        float h00 = __bfloat162float(__float2bfloat16_rn(v00));
        float h01 = __bfloat162float(__float2bfloat16_rn(v01));
        float h10 = __bfloat162float(__float2bfloat16_rn(v10));
        float h11 = __bfloat162float(__float2bfloat16_rn(v11));
        *(uint32_t*)(att_hi + i0) = pack_bf16(h00, h01);
        *(uint32_t*)(att_lo + i0) = pack_bf16(v00 - h00, v01 - h01);
        *(uint32_t*)(att_hi + i1) = pack_bf16(h10, h11);
        *(uint32_t*)(att_lo + i1) = pack_bf16(v10 - h10, v11 - h11);
    }
}

// ---------------------------------------------------------------------------
// Launch
// ---------------------------------------------------------------------------
extern "C" void kernel_launch(void* const* d_in, const int* in_sizes, int n_in,
                              void* d_out, int out_size) {
    const float* x      = (const float*)d_in[0];
    const float* w_qkv  = (const float*)d_in[1];
    const float* w_out  = (const float*)d_in[2];
    const float* b_out  = (const float*)d_in[3];
    float* out = (float*)d_out;

    __nv_bfloat16 *x_hi, *x_lo, *wq_hi, *wq_lo, *wo_hi, *wo_lo;
    __nv_bfloat16 *qkv_hi, *qkv_lo, *a_hi, *a_lo;
    cudaGetSymbolAddress((void**)&x_hi,   g_x_hi);
    cudaGetSymbolAddress((void**)&x_lo,   g_x_lo);
    cudaGetSymbolAddress((void**)&wq_hi,  g_wqkv_hi);
    cudaGetSymbolAddress((void**)&wq_lo,  g_wqkv_lo);
    cudaGetSymbolAddress((void**)&wo_hi,  g_wout_hi);
    cudaGetSymbolAddress((void**)&wo_lo,  g_wout_lo);
    cudaGetSymbolAddress((void**)&qkv_hi, g_qkv_hi);
    cudaGetSymbolAddress((void**)&qkv_lo, g_qkv_lo);
    cudaGetSymbolAddress((void**)&a_hi,   g_att_hi);
    cudaGetSymbolAddress((void**)&a_lo,   g_att_lo);

    cudaFuncSetAttribute(attn_mma,
                         cudaFuncAttributeMaxDynamicSharedMemorySize, ATTN_SMEM);
    cudaFuncSetAttribute((const void*)gemm_mma<false, true>,
                         cudaFuncAttributeMaxDynamicSharedMemorySize, GEMM_SMEM);
    cudaFuncSetAttribute((const void*)gemm_mma<true, false>,
                         cudaFuncAttributeMaxDynamicSharedMemorySize, GEMM_SMEM);

    // 0) bf16 hi/lo splits of inputs
    {
        int n4 = ROWS * EMB / 4;
        split_bf16<<<(n4 + 255) / 256, 256>>>((const float4*)x,
            (__nv_bfloat162*)x_hi, (__nv_bfloat162*)x_lo, n4);
        n4 = F3 * EMB / 4;
        split_bf16<<<(n4 + 255) / 256, 256>>>((const float4*)w_qkv,
            (__nv_bfloat162*)wq_hi, (__nv_bfloat162*)wq_lo, n4);
        n4 = EMB * EMB / 4;
        split_bf16<<<(n4 + 255) / 256, 256>>>((const float4*)w_out,
            (__nv_bfloat162*)wo_hi, (__nv_bfloat162*)wo_lo, n4);
    }

    // 1) QKV projection -> bf16 hi/lo qkv directly
    gemm_mma<false, true><<<dim3(F3 / 128, ROWS / 128), 256, GEMM_SMEM>>>(
        x_hi, x_lo, wq_hi, wq_lo, nullptr, nullptr, qkv_hi, qkv_lo, F3, EMB);

    // 2) Tensor-core causal flash attention -> att hi/lo
    attn_mma<<<dim3(SEQ / 128, NH, BS), 256, ATTN_SMEM>>>(qkv_hi, qkv_lo, a_hi, a_lo);

    // 3) Output projection + bias -> fp32 out
    gemm_mma<true, false><<<dim3(EMB / 128, ROWS / 128), 256, GEMM_SMEM>>>(
        a_hi, a_lo, wo_hi, wo_lo, b_out, out, nullptr, nullptr, EMB, EMB);
}

// round 5
// speedup vs baseline: 2.7337x; 1.3181x over previous
#include <cuda_runtime.h>
#include <cuda_bf16.h>
#include <cstdint>
#include <math.h>

// Problem constants (fixed shapes)
#define BS   2
#define SEQ  2048
#define EMB  1024
#define NH   16
#define HD   64
#define F3   3072   // 3*EMB
#define ROWS (BS * SEQ)   // 4096

// ---------------------------------------------------------------------------
// Scratch (device globals: allocation-free rule)
// ---------------------------------------------------------------------------
__device__ __nv_bfloat16 g_x_hi[ROWS * EMB];
__device__ __nv_bfloat16 g_x_lo[ROWS * EMB];
__device__ __nv_bfloat16 g_wqkv_hi[F3 * EMB];
__device__ __nv_bfloat16 g_wqkv_lo[F3 * EMB];
__device__ __nv_bfloat16 g_wout_hi[EMB * EMB];
__device__ __nv_bfloat16 g_wout_lo[EMB * EMB];
__device__ __nv_bfloat16 g_qkv_hi[ROWS * F3];
__device__ __nv_bfloat16 g_qkv_lo[ROWS * F3];
__device__ __nv_bfloat16 g_att_hi[ROWS * EMB];
__device__ __nv_bfloat16 g_att_lo[ROWS * EMB];

// ---------------------------------------------------------------------------
// helpers
// ---------------------------------------------------------------------------
__device__ __forceinline__ uint32_t smem_u32(const void* p) {
    uint32_t a;
    asm("{ .reg .u64 t; cvta.to.shared.u64 t, %1; cvt.u32.u64 %0, t; }" : "=r"(a) : "l"(p));
    return a;
}
__device__ __forceinline__ void ldsm_x4(uint32_t addr, uint32_t r[4]) {
    asm volatile("ldmatrix.sync.aligned.m8n8.x4.shared.b16 {%0,%1,%2,%3}, [%4];"
                 : "=r"(r[0]), "=r"(r[1]), "=r"(r[2]), "=r"(r[3]) : "r"(addr));
}
__device__ __forceinline__ void ldsm_x4_t(uint32_t addr, uint32_t r[4]) {
    asm volatile("ldmatrix.sync.aligned.m8n8.x4.trans.shared.b16 {%0,%1,%2,%3}, [%4];"
                 : "=r"(r[0]), "=r"(r[1]), "=r"(r[2]), "=r"(r[3]) : "r"(addr));
}
__device__ __forceinline__ void mma16816(float c[4], const uint32_t a[4],
                                         const uint32_t b0, const uint32_t b1) {
    asm volatile(
        "mma.sync.aligned.m16n8k16.row.col.f32.bf16.bf16.f32 "
        "{%0,%1,%2,%3}, {%4,%5,%6,%7}, {%8,%9}, {%0,%1,%2,%3};"
        : "+f"(c[0]), "+f"(c[1]), "+f"(c[2]), "+f"(c[3])
        : "r"(a[0]), "r"(a[1]), "r"(a[2]), "r"(a[3]), "r"(b0), "r"(b1));
}
__device__ __forceinline__ uint32_t pack_bf16(float lo, float hi) {
    uint32_t r;
    asm("cvt.rn.bf16x2.f32 %0, %1, %2;" : "=r"(r) : "f"(hi), "f"(lo));
    return r;
}
__device__ __forceinline__ float ex2(float x) {
    float r;
    asm("ex2.approx.ftz.f32 %0, %1;" : "=f"(r) : "f"(x));
    return r;
}
__device__ __forceinline__ void cp_async16(uint32_t dst, const void* src) {
    asm volatile("cp.async.cg.shared.global [%0], [%1], 16;" :: "r"(dst), "l"(src));
}
#define CP_COMMIT() asm volatile("cp.async.commit_group;" ::: "memory")
#define CP_WAIT1()  asm volatile("cp.async.wait_group 1;" ::: "memory")
#define CP_WAIT0()  asm volatile("cp.async.wait_group 0;" ::: "memory")

// ---------------------------------------------------------------------------
// bf16 hi/lo split (float4 vectorized)
// ---------------------------------------------------------------------------
__global__ void split_bf16(const float4* __restrict__ in,
                           __nv_bfloat162* __restrict__ hi,
                           __nv_bfloat162* __restrict__ lo, int n4) {
    int i = blockIdx.x * blockDim.x + threadIdx.x;
    if (i >= n4) return;
    float4 v = in[i];
    __nv_bfloat16 h0 = __float2bfloat16_rn(v.x);
    __nv_bfloat16 h1 = __float2bfloat16_rn(v.y);
    __nv_bfloat16 h2 = __float2bfloat16_rn(v.z);
    __nv_bfloat16 h3 = __float2bfloat16_rn(v.w);
    __nv_bfloat16 l0 = __float2bfloat16_rn(v.x - __bfloat162float(h0));
    __nv_bfloat16 l1 = __float2bfloat16_rn(v.y - __bfloat162float(h1));
    __nv_bfloat16 l2 = __float2bfloat16_rn(v.z - __bfloat162float(h2));
    __nv_bfloat16 l3 = __float2bfloat16_rn(v.w - __bfloat162float(h3));
    hi[2 * i]     = __nv_bfloat162(h0, h1);
    hi[2 * i + 1] = __nv_bfloat162(h2, h3);
    lo[2 * i]     = __nv_bfloat162(l0, l1);
    lo[2 * i + 1] = __nv_bfloat162(l2, l3);
}

// ---------------------------------------------------------------------------
// mma.sync bf16x3 GEMM, cp.async double-buffered.
// 128x128 CTA tile, 8 warps (warp tile 32x64), BK=32.
// ---------------------------------------------------------------------------
#define SA_STRIDE 40
#define TILE_BYTES (128 * SA_STRIDE * 2)        // 10240
#define STAGE_BYTES (4 * TILE_BYTES)            // 40960
#define GEMM_SMEM (2 * STAGE_BYTES)             // 81920

template <bool HAS_BIAS, bool SPLIT_OUT>
__global__ __launch_bounds__(256)
void gemm_mma(const __nv_bfloat16* __restrict__ Ahi, const __nv_bfloat16* __restrict__ Alo,
              const __nv_bfloat16* __restrict__ Bhi, const __nv_bfloat16* __restrict__ Blo,
              const float* __restrict__ bias, float* __restrict__ C,
              __nv_bfloat16* __restrict__ Chi, __nv_bfloat16* __restrict__ Clo,
              int N, int K) {
    extern __shared__ char smem[];
    const uint32_t sb = smem_u32(smem);

    const int tid  = threadIdx.x;
    const int wid  = tid >> 5;
    const int lane = tid & 31;
    const int n0 = blockIdx.x * 128;
    const int m0 = blockIdx.y * 128;
    const int wm = (wid & 3) * 32;
    const int wn = (wid >> 2) * 64;

    const int trow  = lane & 7;
    const int tquad = lane >> 3;
    const int a_row_off = (tquad & 1) * 8 + trow;
    const int a_col_off = (tquad >> 1) * 8;
    const int b_row_off = (tquad >> 1) * 8 + trow;
    const int b_col_off = (tquad & 1) * 8;

    float acc[2][8][4];
#pragma unroll
    for (int mt = 0; mt < 2; mt++)
#pragma unroll
        for (int nt = 0; nt < 8; nt++)
#pragma unroll
            for (int j = 0; j < 4; j++) acc[mt][nt][j] = 0.0f;

    // per-thread load coordinates (2 x 16B per tile per stage)
    auto load_stage = [&](int stage, int k0) {
        uint32_t sbase = sb + stage * STAGE_BYTES;
#pragma unroll
        for (int i = 0; i < 2; i++) {
            int idx = tid * 2 + i;
            int row = idx >> 2, q = idx & 3;
            uint32_t soff = (uint32_t)(row * SA_STRIDE + q * 8) * 2;
            size_t ga = (size_t)(m0 + row) * K + k0 + q * 8;
            size_t gb = (size_t)(n0 + row) * K + k0 + q * 8;
            cp_async16(sbase + soff,                  Ahi + ga);
            cp_async16(sbase + TILE_BYTES + soff,     Alo + ga);
            cp_async16(sbase + 2 * TILE_BYTES + soff, Bhi + gb);
            cp_async16(sbase + 3 * TILE_BYTES + soff, Blo + gb);
        }
        CP_COMMIT();
    };

    const int NC = K >> 5;
    load_stage(0, 0);

    for (int c = 0; c < NC; c++) {
        const bool pref = (c + 1 < NC);
        if (pref) load_stage((c + 1) & 1, (c + 1) * 32);
        if (pref) CP_WAIT1(); else CP_WAIT0();
        __syncthreads();

        const uint32_t AH = sb + (c & 1) * STAGE_BYTES;
        const uint32_t AL = AH + TILE_BYTES;
        const uint32_t BH = AH + 2 * TILE_BYTES;
        const uint32_t BL = AH + 3 * TILE_BYTES;

#pragma unroll
        for (int ks = 0; ks < 2; ks++) {
            const int kk = ks * 16;
            uint32_t ah[2][4], al[2][4], bh[4][4], bl[4][4];
#pragma unroll
            for (int mt = 0; mt < 2; mt++) {
                uint32_t ao = (uint32_t)((wm + mt * 16 + a_row_off) * SA_STRIDE +
                                         kk + a_col_off) * 2;
                ldsm_x4(AH + ao, ah[mt]);
                ldsm_x4(AL + ao, al[mt]);
            }
#pragma unroll
            for (int np = 0; np < 4; np++) {
                uint32_t bo = (uint32_t)((wn + np * 16 + b_row_off) * SA_STRIDE +
                                         kk + b_col_off) * 2;
                ldsm_x4(BH + bo, bh[np]);
                ldsm_x4(BL + bo, bl[np]);
            }
#pragma unroll
            for (int mt = 0; mt < 2; mt++)
#pragma unroll
                for (int np = 0; np < 4; np++) {
                    mma16816(acc[mt][2 * np],     ah[mt], bh[np][0], bh[np][1]);
                    mma16816(acc[mt][2 * np + 1], ah[mt], bh[np][2], bh[np][3]);
                }
#pragma unroll
            for (int mt = 0; mt < 2; mt++)
#pragma unroll
                for (int np = 0; np < 4; np++) {
                    mma16816(acc[mt][2 * np],     ah[mt], bl[np][0], bl[np][1]);
                    mma16816(acc[mt][2 * np + 1], ah[mt], bl[np][2], bl[np][3]);
                }
#pragma unroll
            for (int mt = 0; mt < 2; mt++)
#pragma unroll
                for (int np = 0; np < 4; np++) {
                    mma16816(acc[mt][2 * np],     al[mt], bh[np][0], bh[np][1]);
                    mma16816(acc[mt][2 * np + 1], al[mt], bh[np][2], bh[np][3]);
                }
        }
        __syncthreads();
    }

    const int g  = lane >> 2;
    const int t2 = (lane & 3) * 2;
#pragma unroll
    for (int mt = 0; mt < 2; mt++) {
        int mrow0 = m0 + wm + mt * 16 + g;
#pragma unroll
        for (int nt = 0; nt < 8; nt++) {
            int n = n0 + wn + nt * 8 + t2;
            float b0 = 0.f, b1 = 0.f;
            if (HAS_BIAS) { b0 = bias[n]; b1 = bias[n + 1]; }
            float v00 = acc[mt][nt][0] + b0, v01 = acc[mt][nt][1] + b1;
            float v10 = acc[mt][nt][2] + b0, v11 = acc[mt][nt][3] + b1;
            if (SPLIT_OUT) {
                size_t i0 = (size_t)mrow0 * N + n;
                size_t i1 = (size_t)(mrow0 + 8) * N + n;
                float h00 = __bfloat162float(__float2bfloat16_rn(v00));
                float h01 = __bfloat162float(__float2bfloat16_rn(v01));
                float h10 = __bfloat162float(__float2bfloat16_rn(v10));
                float h11 = __bfloat162float(__float2bfloat16_rn(v11));
                *(uint32_t*)(Chi + i0) = pack_bf16(h00, h01);
                *(uint32_t*)(Clo + i0) = pack_bf16(v00 - h00, v01 - h01);
                *(uint32_t*)(Chi + i1) = pack_bf16(h10, h11);
                *(uint32_t*)(Clo + i1) = pack_bf16(v10 - h10, v11 - h11);
            } else {
                *(float2*)(C + (size_t)mrow0 * N + n)       = make_float2(v00, v01);
                *(float2*)(C + (size_t)(mrow0 + 8) * N + n) = make_float2(v10, v11);
            }
        }
    }
}

// ---------------------------------------------------------------------------
// Tensor-core causal flash attention (bf16x3), cp.async double-buffered.
// BM=128, BN=64, HD=64, 8 warps.
// ---------------------------------------------------------------------------
#define AT_STRIDE 72
#define AT_TILE (64 * AT_STRIDE * 2)       // 9216 bytes
#define AT_STAGE (4 * AT_TILE)             // 36864: KH, KL, VH, VL
#define ATTN_SMEM (2 * AT_STAGE)           // 73728

#define SCALE2 0.1803368801111244f         // 0.125 * log2(e)

__global__ __launch_bounds__(256)
void attn_mma(const __nv_bfloat16* __restrict__ qkv_hi,
              const __nv_bfloat16* __restrict__ qkv_lo,
              __nv_bfloat16* __restrict__ att_hi,
              __nv_bfloat16* __restrict__ att_lo) {
    extern __shared__ char smem[];
    const uint32_t sb = smem_u32(smem);

    const int tid  = threadIdx.x;
    const int wid  = tid >> 5;
    const int lane = tid & 31;
    const int it = blockIdx.x;      // 128-row query tile
    const int h  = blockIdx.y;
    const int b  = blockIdx.z;
    const size_t hbase = (size_t)b * SEQ * F3 + (size_t)h * 192;

    // ---- Stage Q (128x64 hi & lo) through stage-0 buffers ----
#pragma unroll
    for (int i = 0; i < 2; i++) {
        int idx = tid * 2 + i;        // 0..511
        int row = idx >> 3, q = idx & 7;
        uint32_t soff = (uint32_t)(row * AT_STRIDE + q * 8) * 2;
        size_t glo = hbase + (size_t)(it * 128 + row) * F3 + q * 8;
        size_t ghi = hbase + (size_t)(it * 128 + 64 + row) * F3 + q * 8;
        *(uint4*)(smem + soff)               = *(const uint4*)(qkv_hi + glo);
        *(uint4*)(smem + AT_TILE + soff)     = *(const uint4*)(qkv_lo + glo);
        *(uint4*)(smem + 2 * AT_TILE + soff) = *(const uint4*)(qkv_hi + ghi);
        *(uint4*)(smem + 3 * AT_TILE + soff) = *(const uint4*)(qkv_lo + ghi);
    }
    __syncthreads();

    // Q fragments (register resident): warp w owns rows 16*(w&3) + 64*(w>>2)
    uint32_t qh[4][4], ql[4][4];
    {
        uint32_t hb = (wid < 4) ? sb : sb + 2 * AT_TILE;
        uint32_t lb = (wid < 4) ? sb + AT_TILE : sb + 3 * AT_TILE;
        uint32_t qoff = (uint32_t)((16 * (wid & 3) + (lane & 15)) * AT_STRIDE +
                                   (lane >> 4) * 8) * 2;
#pragma unroll
        for (int ks = 0; ks < 4; ks++) {
            ldsm_x4(hb + qoff + ks * 32, qh[ks]);
            ldsm_x4(lb + qoff + ks * 32, ql[ks]);
        }
    }
    __syncthreads();   // everyone done reading Q before stage-0 overwrite

    auto load_kv = [&](int stage, int jt) {
        uint32_t sbase = sb + stage * AT_STAGE;
#pragma unroll
        for (int i = 0; i < 2; i++) {
            int idx = tid * 2 + i;
            int row = idx >> 3, q = idx & 7;
            uint32_t soff = (uint32_t)(row * AT_STRIDE + q * 8) * 2;
            size_t gr = hbase + (size_t)(jt * 64 + row) * F3 + q * 8;
            cp_async16(sbase + soff,               qkv_hi + gr + 64);    // K hi
            cp_async16(sbase + AT_TILE + soff,     qkv_lo + gr + 64);    // K lo
            cp_async16(sbase + 2 * AT_TILE + soff, qkv_hi + gr + 128);   // V hi
            cp_async16(sbase + 3 * AT_TILE + soff, qkv_lo + gr + 128);   // V lo
        }
        CP_COMMIT();
    };

    float m2[2] = {-1e30f, -1e30f}, l[2] = {0.f, 0.f};
    float o[8][4];
#pragma unroll
    for (int dt = 0; dt < 8; dt++)
#pragma unroll
        for (int j = 0; j < 4; j++) o[dt][j] = 0.0f;

    const int rbase = 128 * it + 16 * (wid & 3) + 64 * (wid >> 2);
    const int g  = lane >> 2;
    const int t2 = (lane & 3) * 2;
    const uint32_t koff = (uint32_t)(((lane >> 4) * 8 + (lane & 7)) * AT_STRIDE +
                                     ((lane >> 3) & 1) * 8) * 2;
    const uint32_t voff = (uint32_t)((lane & 15) * AT_STRIDE + (lane >> 4) * 8) * 2;

    const int jt_max = 2 * it + 2;
    load_kv(0, 0);

    for (int jt = 0; jt < jt_max; jt++) {
        const bool pref = (jt + 1 < jt_max);
        if (pref) load_kv((jt + 1) & 1, jt + 1);
        if (pref) CP_WAIT1(); else CP_WAIT0();
        __syncthreads();

        const uint32_t KH = sb + (jt & 1) * AT_STAGE;
        const uint32_t KL = KH + AT_TILE;
        const uint32_t VH = KH + 2 * AT_TILE;
        const uint32_t VL = KH + 3 * AT_TILE;

        // ---- S = Q K^T (hoisted hi/lo fragments) ----
        float s[8][4];
#pragma unroll
        for (int nt = 0; nt < 8; nt++)
#pragma unroll
            for (int j = 0; j < 4; j++) s[nt][j] = 0.0f;

#pragma unroll
        for (int ks = 0; ks < 4; ks++) {
            uint32_t kh[4][4], kl[4][4];
#pragma unroll
            for (int np = 0; np < 4; np++) {
                uint32_t bo = koff + (uint32_t)(np * 16 * AT_STRIDE + ks * 16) * 2;
                ldsm_x4(KH + bo, kh[np]);
                ldsm_x4(KL + bo, kl[np]);
            }
#pragma unroll
            for (int np = 0; np < 4; np++) {
                mma16816(s[2 * np],     qh[ks], kh[np][0], kh[np][1]);
                mma16816(s[2 * np + 1], qh[ks], kh[np][2], kh[np][3]);
            }
#pragma unroll
            for (int np = 0; np < 4; np++) {
                mma16816(s[2 * np],     qh[ks], kl[np][0], kl[np][1]);
                mma16816(s[2 * np + 1], qh[ks], kl[np][2], kl[np][3]);
            }
#pragma unroll
            for (int np = 0; np < 4; np++) {
                mma16816(s[2 * np],     ql[ks], kh[np][0], kh[np][1]);
                mma16816(s[2 * np + 1], ql[ks], kh[np][2], kh[np][3]);
            }
        }

        // ---- scale (+ causal mask on diagonal tiles) ----
        const bool diag = (jt >= 2 * it);
#pragma unroll
        for (int nt = 0; nt < 8; nt++)
#pragma unroll
            for (int j = 0; j < 4; j++) {
                float t = s[nt][j] * SCALE2;
                if (diag) {
                    int col = jt * 64 + nt * 8 + t2 + (j & 1);
                    int row = rbase + g + 8 * (j >> 1);
                    if (col > row) t = -1e30f;
                }
                s[nt][j] = t;
            }

        // ---- online softmax ----
        float rmax[2] = {-1e30f, -1e30f};
#pragma unroll
        for (int nt = 0; nt < 8; nt++) {
            rmax[0] = fmaxf(rmax[0], fmaxf(s[nt][0], s[nt][1]));
            rmax[1] = fmaxf(rmax[1], fmaxf(s[nt][2], s[nt][3]));
        }
#pragma unroll
        for (int off = 1; off <= 2; off <<= 1) {
            rmax[0] = fmaxf(rmax[0], __shfl_xor_sync(0xffffffffu, rmax[0], off));
            rmax[1] = fmaxf(rmax[1], __shfl_xor_sync(0xffffffffu, rmax[1], off));
        }
        float alpha[2], rsum[2];
#pragma unroll
        for (int r = 0; r < 2; r++) {
            float mnew = fmaxf(m2[r], rmax[r]);
            alpha[r] = ex2(m2[r] - mnew);
            m2[r] = mnew;
            rsum[r] = 0.f;
        }
#pragma unroll
        for (int nt = 0; nt < 8; nt++) {
            s[nt][0] = ex2(s[nt][0] - m2[0]);
            s[nt][1] = ex2(s[nt][1] - m2[0]);
            s[nt][2] = ex2(s[nt][2] - m2[1]);
            s[nt][3] = ex2(s[nt][3] - m2[1]);
            rsum[0] += s[nt][0] + s[nt][1];
            rsum[1] += s[nt][2] + s[nt][3];
        }
#pragma unroll
        for (int off = 1; off <= 2; off <<= 1) {
            rsum[0] += __shfl_xor_sync(0xffffffffu, rsum[0], off);
            rsum[1] += __shfl_xor_sync(0xffffffffu, rsum[1], off);
        }
#pragma unroll
        for (int r = 0; r < 2; r++) l[r] = l[r] * alpha[r] + rsum[r];
#pragma unroll
        for (int dt = 0; dt < 8; dt++) {
            o[dt][0] *= alpha[0];
            o[dt][1] *= alpha[0];
            o[dt][2] *= alpha[1];
            o[dt][3] *= alpha[1];
        }

        // ---- pack P into A-fragments (hi + lo) ----
        uint32_t ph[4][4], pl[4][4];
#pragma unroll
        for (int ks = 0; ks < 4; ks++) {
#pragma unroll
            for (int half = 0; half < 2; half++) {
                int nt = 2 * ks + half;
                float p0 = s[nt][0], p1 = s[nt][1], p2 = s[nt][2], p3 = s[nt][3];
                float h0 = __bfloat162float(__float2bfloat16_rn(p0));
                float h1 = __bfloat162float(__float2bfloat16_rn(p1));
                float h2 = __bfloat162float(__float2bfloat16_rn(p2));
                float h3 = __bfloat162float(__float2bfloat16_rn(p3));
                ph[ks][2 * half]     = pack_bf16(h0, h1);
                ph[ks][2 * half + 1] = pack_bf16(h2, h3);
                pl[ks][2 * half]     = pack_bf16(p0 - h0, p1 - h1);
                pl[ks][2 * half + 1] = pack_bf16(p2 - h2, p3 - h3);
            }
        }

        // ---- O += P V (hoisted hi/lo V fragments; ldmatrix.trans) ----
#pragma unroll
        for (int ks = 0; ks < 4; ks++) {
            uint32_t vh[4][4], vl[4][4];
#pragma unroll
            for (int np = 0; np < 4; np++) {
                uint32_t bo = voff + (uint32_t)(ks * 16 * AT_STRIDE + np * 16) * 2;
                ldsm_x4_t(VH + bo, vh[np]);
                ldsm_x4_t(VL + bo, vl[np]);
            }
#pragma unroll
            for (int np = 0; np < 4; np++) {
                mma16816(o[2 * np],     ph[ks], vh[np][0], vh[np][1]);
                mma16816(o[2 * np + 1], ph[ks], vh[np][2], vh[np][3]);
            }
#pragma unroll
            for (int np = 0; np < 4; np++) {
                mma16816(o[2 * np],     ph[ks], vl[np][0], vl[np][1]);
                mma16816(o[2 * np + 1], ph[ks], vl[np][2], vl[np][3]);
            }
#pragma unroll
            for (int np = 0; np < 4; np++) {
                mma16816(o[2 * np],     pl[ks], vh[np][0], vh[np][1]);
                mma16816(o[2 * np + 1], pl[ks], vh[np][2], vh[np][3]);
            }
        }
        __syncthreads();
    }

    // ---- epilogue: O/l -> att hi/lo ----
    float inv0 = 1.0f / l[0], inv1 = 1.0f / l[1];
#pragma unroll
    for (int dt = 0; dt < 8; dt++) {
        int col = h * 64 + dt * 8 + t2;
        size_t i0 = ((size_t)b * SEQ + rbase + g) * EMB + col;
        size_t i1 = ((size_t)b * SEQ + rbase + g + 8) * EMB + col;
        float v00 = o[dt][0] * inv0, v01 = o[dt][1] * inv0;
        float v10 = o[dt][2] * inv1, v11 = o[dt][3] * inv1;
        float h00 = __bfloat162float(__float2bfloat16_rn(v00));
        float h01 = __bfloat162float(__float2bfloat16_rn(v01));
        float h10 = __bfloat162float(__float2bfloat16_rn(v10));
        float h11 = __bfloat162float(__float2bfloat16_rn(v11));
        *(uint32_t*)(att_hi + i0) = pack_bf16(h00, h01);
        *(uint32_t*)(att_lo + i0) = pack_bf16(v00 - h00, v01 - h01);
        *(uint32_t*)(att_hi + i1) = pack_bf16(h10, h11);
        *(uint32_t*)(att_lo + i1) = pack_bf16(v10 - h10, v11 - h11);
    }
}

// ---------------------------------------------------------------------------
// Launch
// ---------------------------------------------------------------------------
extern "C" void kernel_launch(void* const* d_in, const int* in_sizes, int n_in,
                              void* d_out, int out_size) {
    const float* x      = (const float*)d_in[0];
    const float* w_qkv  = (const float*)d_in[1];
    const float* w_out  = (const float*)d_in[2];
    const float* b_out  = (const float*)d_in[3];
    float* out = (float*)d_out;

    __nv_bfloat16 *x_hi, *x_lo, *wq_hi, *wq_lo, *wo_hi, *wo_lo;
    __nv_bfloat16 *qkv_hi, *qkv_lo, *a_hi, *a_lo;
    cudaGetSymbolAddress((void**)&x_hi,   g_x_hi);
    cudaGetSymbolAddress((void**)&x_lo,   g_x_lo);
    cudaGetSymbolAddress((void**)&wq_hi,  g_wqkv_hi);
    cudaGetSymbolAddress((void**)&wq_lo,  g_wqkv_lo);
    cudaGetSymbolAddress((void**)&wo_hi,  g_wout_hi);
    cudaGetSymbolAddress((void**)&wo_lo,  g_wout_lo);
    cudaGetSymbolAddress((void**)&qkv_hi, g_qkv_hi);
    cudaGetSymbolAddress((void**)&qkv_lo, g_qkv_lo);
    cudaGetSymbolAddress((void**)&a_hi,   g_att_hi);
    cudaGetSymbolAddress((void**)&a_lo,   g_att_lo);

    cudaFuncSetAttribute(attn_mma,
                         cudaFuncAttributeMaxDynamicSharedMemorySize, ATTN_SMEM);
    cudaFuncSetAttribute((const void*)gemm_mma<false, true>,
                         cudaFuncAttributeMaxDynamicSharedMemorySize, GEMM_SMEM);
    cudaFuncSetAttribute((const void*)gemm_mma<true, false>,
                         cudaFuncAttributeMaxDynamicSharedMemorySize, GEMM_SMEM);

    // 0) bf16 hi/lo splits of inputs
    {
        int n4 = ROWS * EMB / 4;
        split_bf16<<<(n4 + 255) / 256, 256>>>((const float4*)x,
            (__nv_bfloat162*)x_hi, (__nv_bfloat162*)x_lo, n4);
        n4 = F3 * EMB / 4;
        split_bf16<<<(n4 + 255) / 256, 256>>>((const float4*)w_qkv,
            (__nv_bfloat162*)wq_hi, (__nv_bfloat162*)wq_lo, n4);
        n4 = EMB * EMB / 4;
        split_bf16<<<(n4 + 255) / 256, 256>>>((const float4*)w_out,
            (__nv_bfloat162*)wo_hi, (__nv_bfloat162*)wo_lo, n4);
    }

    // 1) QKV projection -> bf16 hi/lo qkv directly
    gemm_mma<false, true><<<dim3(F3 / 128, ROWS / 128), 256, GEMM_SMEM>>>(
        x_hi, x_lo, wq_hi, wq_lo, nullptr, nullptr, qkv_hi, qkv_lo, F3, EMB);

    // 2) Tensor-core causal flash attention -> att hi/lo
    attn_mma<<<dim3(SEQ / 128, NH, BS), 256, ATTN_SMEM>>>(qkv_hi, qkv_lo, a_hi, a_lo);

    // 3) Output projection + bias -> fp32 out
    gemm_mma<true, false><<<dim3(EMB / 128, ROWS / 128), 256, GEMM_SMEM>>>(
        a_hi, a_lo, wo_hi, wo_lo, b_out, out, nullptr, nullptr, EMB, EMB);
}

// round 6
// speedup vs baseline: 2.8095x; 1.0277x over previous
#include <cuda_runtime.h>
#include <cuda_bf16.h>
#include <cstdint>
#include <math.h>

// Problem constants (fixed shapes)
#define BS   2
#define SEQ  2048
#define EMB  1024
#define NH   16
#define HD   64
#define F3   3072   // 3*EMB
#define ROWS (BS * SEQ)   // 4096

// ---------------------------------------------------------------------------
// Scratch (device globals: allocation-free rule)
// ---------------------------------------------------------------------------
__device__ __nv_bfloat16 g_x_hi[ROWS * EMB];
__device__ __nv_bfloat16 g_x_lo[ROWS * EMB];
__device__ __nv_bfloat16 g_wqkv_hi[F3 * EMB];
__device__ __nv_bfloat16 g_wqkv_lo[F3 * EMB];
__device__ __nv_bfloat16 g_wout_hi[EMB * EMB];
__device__ __nv_bfloat16 g_wout_lo[EMB * EMB];
__device__ __nv_bfloat16 g_qkv_hi[ROWS * F3];
__device__ __nv_bfloat16 g_qkv_lo[ROWS * F3];
__device__ __nv_bfloat16 g_att_hi[ROWS * EMB];
__device__ __nv_bfloat16 g_att_lo[ROWS * EMB];

// ---------------------------------------------------------------------------
// helpers
// ---------------------------------------------------------------------------
__device__ __forceinline__ uint32_t smem_u32(const void* p) {
    uint32_t a;
    asm("{ .reg .u64 t; cvta.to.shared.u64 t, %1; cvt.u32.u64 %0, t; }" : "=r"(a) : "l"(p));
    return a;
}
__device__ __forceinline__ void ldsm_x4(uint32_t addr, uint32_t r[4]) {
    asm volatile("ldmatrix.sync.aligned.m8n8.x4.shared.b16 {%0,%1,%2,%3}, [%4];"
                 : "=r"(r[0]), "=r"(r[1]), "=r"(r[2]), "=r"(r[3]) : "r"(addr));
}
__device__ __forceinline__ void ldsm_x4_t(uint32_t addr, uint32_t r[4]) {
    asm volatile("ldmatrix.sync.aligned.m8n8.x4.trans.shared.b16 {%0,%1,%2,%3}, [%4];"
                 : "=r"(r[0]), "=r"(r[1]), "=r"(r[2]), "=r"(r[3]) : "r"(addr));
}
__device__ __forceinline__ void mma16816(float c[4], const uint32_t a[4],
                                         const uint32_t b0, const uint32_t b1) {
    asm volatile(
        "mma.sync.aligned.m16n8k16.row.col.f32.bf16.bf16.f32 "
        "{%0,%1,%2,%3}, {%4,%5,%6,%7}, {%8,%9}, {%0,%1,%2,%3};"
        : "+f"(c[0]), "+f"(c[1]), "+f"(c[2]), "+f"(c[3])
        : "r"(a[0]), "r"(a[1]), "r"(a[2]), "r"(a[3]), "r"(b0), "r"(b1));
}
__device__ __forceinline__ uint32_t pack_bf16(float lo, float hi) {
    uint32_t r;
    asm("cvt.rn.bf16x2.f32 %0, %1, %2;" : "=r"(r) : "f"(hi), "f"(lo));
    return r;
}
__device__ __forceinline__ float ex2(float x) {
    float r;
    asm("ex2.approx.ftz.f32 %0, %1;" : "=f"(r) : "f"(x));
    return r;
}
__device__ __forceinline__ void cp_async16(uint32_t dst, const void* src) {
    asm volatile("cp.async.cg.shared.global [%0], [%1], 16;" :: "r"(dst), "l"(src));
}
#define CP_COMMIT() asm volatile("cp.async.commit_group;" ::: "memory")
#define CP_WAIT1()  asm volatile("cp.async.wait_group 1;" ::: "memory")
#define CP_WAIT0()  asm volatile("cp.async.wait_group 0;" ::: "memory")

// ---------------------------------------------------------------------------
// bf16 hi/lo split (float4 vectorized)
// ---------------------------------------------------------------------------
__global__ void split_bf16(const float4* __restrict__ in,
                           __nv_bfloat162* __restrict__ hi,
                           __nv_bfloat162* __restrict__ lo, int n4) {
    int i = blockIdx.x * blockDim.x + threadIdx.x;
    if (i >= n4) return;
    float4 v = in[i];
    __nv_bfloat16 h0 = __float2bfloat16_rn(v.x);
    __nv_bfloat16 h1 = __float2bfloat16_rn(v.y);
    __nv_bfloat16 h2 = __float2bfloat16_rn(v.z);
    __nv_bfloat16 h3 = __float2bfloat16_rn(v.w);
    __nv_bfloat16 l0 = __float2bfloat16_rn(v.x - __bfloat162float(h0));
    __nv_bfloat16 l1 = __float2bfloat16_rn(v.y - __bfloat162float(h1));
    __nv_bfloat16 l2 = __float2bfloat16_rn(v.z - __bfloat162float(h2));
    __nv_bfloat16 l3 = __float2bfloat16_rn(v.w - __bfloat162float(h3));
    hi[2 * i]     = __nv_bfloat162(h0, h1);
    hi[2 * i + 1] = __nv_bfloat162(h2, h3);
    lo[2 * i]     = __nv_bfloat162(l0, l1);
    lo[2 * i + 1] = __nv_bfloat162(l2, l3);
}

// ---------------------------------------------------------------------------
// mma.sync bf16x3 GEMM, cp.async double-buffered.
// CTA tile 256x128, 8 warps, warp tile 64x64 (4 m-tiles x 8 n-tiles), BK=32.
// Fragment sequencing per k-step keeps live regs bounded:
//   ldsm ah,bh -> hh pass; ldsm bl -> hl pass; ldsm al -> lh pass.
// ---------------------------------------------------------------------------
#define SA_STRIDE 40
#define ATILE_B (256 * SA_STRIDE * 2)           // 20480
#define BTILE_B (128 * SA_STRIDE * 2)           // 10240
#define STAGE_B (2 * ATILE_B + 2 * BTILE_B)     // 61440
#define GEMM_SMEM (2 * STAGE_B)                 // 122880

template <bool HAS_BIAS, bool SPLIT_OUT>
__global__ __launch_bounds__(256, 1)
void gemm_mma(const __nv_bfloat16* __restrict__ Ahi, const __nv_bfloat16* __restrict__ Alo,
              const __nv_bfloat16* __restrict__ Bhi, const __nv_bfloat16* __restrict__ Blo,
              const float* __restrict__ bias, float* __restrict__ C,
              __nv_bfloat16* __restrict__ Chi, __nv_bfloat16* __restrict__ Clo,
              int N, int K) {
    extern __shared__ char smem[];
    const uint32_t sb = smem_u32(smem);

    const int tid  = threadIdx.x;
    const int wid  = tid >> 5;
    const int lane = tid & 31;
    const int n0 = blockIdx.x * 128;
    const int m0 = blockIdx.y * 256;
    const int wm = (wid & 3) * 64;   // warp m-offset (4 warps in m)
    const int wn = (wid >> 2) * 64;  // warp n-offset (2 warps in n)

    const int trow  = lane & 7;
    const int tquad = lane >> 3;
    const int a_row_off = (tquad & 1) * 8 + trow;
    const int a_col_off = (tquad >> 1) * 8;
    const int b_row_off = (tquad >> 1) * 8 + trow;
    const int b_col_off = (tquad & 1) * 8;

    float acc[4][8][4];
#pragma unroll
    for (int mt = 0; mt < 4; mt++)
#pragma unroll
        for (int nt = 0; nt < 8; nt++)
#pragma unroll
            for (int j = 0; j < 4; j++) acc[mt][nt][j] = 0.0f;

    // stage loader: A 256x32 hi/lo (4 uint4/thread each), B 128x32 hi/lo (2 each)
    auto load_stage = [&](int stage, int k0) {
        uint32_t s0 = sb + stage * STAGE_B;
#pragma unroll
        for (int i = 0; i < 4; i++) {
            int idx = tid + 256 * i;          // 0..1023
            int row = idx >> 2, q = idx & 3;
            uint32_t soff = (uint32_t)(row * SA_STRIDE + q * 8) * 2;
            size_t ga = (size_t)(m0 + row) * K + k0 + q * 8;
            cp_async16(s0 + soff,            Ahi + ga);
            cp_async16(s0 + ATILE_B + soff,  Alo + ga);
        }
#pragma unroll
        for (int i = 0; i < 2; i++) {
            int idx = tid + 256 * i;          // 0..511
            int row = idx >> 2, q = idx & 3;
            uint32_t soff = (uint32_t)(row * SA_STRIDE + q * 8) * 2;
            size_t gb = (size_t)(n0 + row) * K + k0 + q * 8;
            cp_async16(s0 + 2 * ATILE_B + soff,           Bhi + gb);
            cp_async16(s0 + 2 * ATILE_B + BTILE_B + soff, Blo + gb);
        }
        CP_COMMIT();
    };

    const int NC = K >> 5;
    load_stage(0, 0);

    for (int c = 0; c < NC; c++) {
        const bool pref = (c + 1 < NC);
        if (pref) load_stage((c + 1) & 1, (c + 1) * 32);
        if (pref) CP_WAIT1(); else CP_WAIT0();
        __syncthreads();

        const uint32_t AH = sb + (c & 1) * STAGE_B;
        const uint32_t AL = AH + ATILE_B;
        const uint32_t BH = AH + 2 * ATILE_B;
        const uint32_t BL = BH + BTILE_B;

#pragma unroll
        for (int ks = 0; ks < 2; ks++) {
            const int kk = ks * 16;
            uint32_t ah[4][4], bh[4][4];
#pragma unroll
            for (int mt = 0; mt < 4; mt++) {
                uint32_t ao = (uint32_t)((wm + mt * 16 + a_row_off) * SA_STRIDE +
                                         kk + a_col_off) * 2;
                ldsm_x4(AH + ao, ah[mt]);
            }
#pragma unroll
            for (int np = 0; np < 4; np++) {
                uint32_t bo = (uint32_t)((wn + np * 16 + b_row_off) * SA_STRIDE +
                                         kk + b_col_off) * 2;
                ldsm_x4(BH + bo, bh[np]);
            }
            // pass hh
#pragma unroll
            for (int mt = 0; mt < 4; mt++)
#pragma unroll
                for (int np = 0; np < 4; np++) {
                    mma16816(acc[mt][2 * np],     ah[mt], bh[np][0], bh[np][1]);
                    mma16816(acc[mt][2 * np + 1], ah[mt], bh[np][2], bh[np][3]);
                }
            // pass hl
            {
                uint32_t bl[4][4];
#pragma unroll
                for (int np = 0; np < 4; np++) {
                    uint32_t bo = (uint32_t)((wn + np * 16 + b_row_off) * SA_STRIDE +
                                             kk + b_col_off) * 2;
                    ldsm_x4(BL + bo, bl[np]);
                }
#pragma unroll
                for (int mt = 0; mt < 4; mt++)
#pragma unroll
                    for (int np = 0; np < 4; np++) {
                        mma16816(acc[mt][2 * np],     ah[mt], bl[np][0], bl[np][1]);
                        mma16816(acc[mt][2 * np + 1], ah[mt], bl[np][2], bl[np][3]);
                    }
            }
            // pass lh
            {
                uint32_t al[4][4];
#pragma unroll
                for (int mt = 0; mt < 4; mt++) {
                    uint32_t ao = (uint32_t)((wm + mt * 16 + a_row_off) * SA_STRIDE +
                                             kk + a_col_off) * 2;
                    ldsm_x4(AL + ao, al[mt]);
                }
#pragma unroll
                for (int mt = 0; mt < 4; mt++)
#pragma unroll
                    for (int np = 0; np < 4; np++) {
                        mma16816(acc[mt][2 * np],     al[mt], bh[np][0], bh[np][1]);
                        mma16816(acc[mt][2 * np + 1], al[mt], bh[np][2], bh[np][3]);
                    }
            }
        }
        __syncthreads();
    }

    const int g  = lane >> 2;
    const int t2 = (lane & 3) * 2;
#pragma unroll
    for (int mt = 0; mt < 4; mt++) {
        int mrow0 = m0 + wm + mt * 16 + g;
#pragma unroll
        for (int nt = 0; nt < 8; nt++) {
            int n = n0 + wn + nt * 8 + t2;
            float b0 = 0.f, b1 = 0.f;
            if (HAS_BIAS) { b0 = bias[n]; b1 = bias[n + 1]; }
            float v00 = acc[mt][nt][0] + b0, v01 = acc[mt][nt][1] + b1;
            float v10 = acc[mt][nt][2] + b0, v11 = acc[mt][nt][3] + b1;
            if (SPLIT_OUT) {
                size_t i0 = (size_t)mrow0 * N + n;
                size_t i1 = (size_t)(mrow0 + 8) * N + n;
                float h00 = __bfloat162float(__float2bfloat16_rn(v00));
                float h01 = __bfloat162float(__float2bfloat16_rn(v01));
                float h10 = __bfloat162float(__float2bfloat16_rn(v10));
                float h11 = __bfloat162float(__float2bfloat16_rn(v11));
                *(uint32_t*)(Chi + i0) = pack_bf16(h00, h01);
                *(uint32_t*)(Clo + i0) = pack_bf16(v00 - h00, v01 - h01);
                *(uint32_t*)(Chi + i1) = pack_bf16(h10, h11);
                *(uint32_t*)(Clo + i1) = pack_bf16(v10 - h10, v11 - h11);
            } else {
                *(float2*)(C + (size_t)mrow0 * N + n)       = make_float2(v00, v01);
                *(float2*)(C + (size_t)(mrow0 + 8) * N + n) = make_float2(v10, v11);
            }
        }
    }
}

// ---------------------------------------------------------------------------
// Tensor-core causal flash attention (bf16x3), cp.async double-buffered.
// BM=128, BN=64, HD=64, 8 warps. Query tiles processed in REVERSE block order
// (heaviest tiles scheduled first -> better causal load balance).
// ---------------------------------------------------------------------------
#define AT_STRIDE 72
#define AT_TILE (64 * AT_STRIDE * 2)       // 9216 bytes
#define AT_STAGE (4 * AT_TILE)             // 36864: KH, KL, VH, VL
#define ATTN_SMEM (2 * AT_STAGE)           // 73728

#define SCALE2 0.1803368801111244f         // 0.125 * log2(e)

__global__ __launch_bounds__(256)
void attn_mma(const __nv_bfloat16* __restrict__ qkv_hi,
              const __nv_bfloat16* __restrict__ qkv_lo,
              __nv_bfloat16* __restrict__ att_hi,
              __nv_bfloat16* __restrict__ att_lo) {
    extern __shared__ char smem[];
    const uint32_t sb = smem_u32(smem);

    const int tid  = threadIdx.x;
    const int wid  = tid >> 5;
    const int lane = tid & 31;
    const int it = gridDim.x - 1 - blockIdx.x;   // big tiles first
    const int h  = blockIdx.y;
    const int b  = blockIdx.z;
    const size_t hbase = (size_t)b * SEQ * F3 + (size_t)h * 192;

    // ---- Stage Q (128x64 hi & lo) through stage-0 buffers ----
#pragma unroll
    for (int i = 0; i < 2; i++) {
        int idx = tid * 2 + i;        // 0..511
        int row = idx >> 3, q = idx & 7;
        uint32_t soff = (uint32_t)(row * AT_STRIDE + q * 8) * 2;
        size_t glo = hbase + (size_t)(it * 128 + row) * F3 + q * 8;
        size_t ghi = hbase + (size_t)(it * 128 + 64 + row) * F3 + q * 8;
        *(uint4*)(smem + soff)               = *(const uint4*)(qkv_hi + glo);
        *(uint4*)(smem + AT_TILE + soff)     = *(const uint4*)(qkv_lo + glo);
        *(uint4*)(smem + 2 * AT_TILE + soff) = *(const uint4*)(qkv_hi + ghi);
        *(uint4*)(smem + 3 * AT_TILE + soff) = *(const uint4*)(qkv_lo + ghi);
    }
    __syncthreads();

    // Q fragments (register resident): warp w owns rows 16*(w&3) + 64*(w>>2)
    uint32_t qh[4][4], ql[4][4];
    {
        uint32_t hb = (wid < 4) ? sb : sb + 2 * AT_TILE;
        uint32_t lb = (wid < 4) ? sb + AT_TILE : sb + 3 * AT_TILE;
        uint32_t qoff = (uint32_t)((16 * (wid & 3) + (lane & 15)) * AT_STRIDE +
                                   (lane >> 4) * 8) * 2;
#pragma unroll
        for (int ks = 0; ks < 4; ks++) {
            ldsm_x4(hb + qoff + ks * 32, qh[ks]);
            ldsm_x4(lb + qoff + ks * 32, ql[ks]);
        }
    }
    __syncthreads();   // everyone done reading Q before stage-0 overwrite

    auto load_kv = [&](int stage, int jt) {
        uint32_t sbase = sb + stage * AT_STAGE;
#pragma unroll
        for (int i = 0; i < 2; i++) {
            int idx = tid * 2 + i;
            int row = idx >> 3, q = idx & 7;
            uint32_t soff = (uint32_t)(row * AT_STRIDE + q * 8) * 2;
            size_t gr = hbase + (size_t)(jt * 64 + row) * F3 + q * 8;
            cp_async16(sbase + soff,               qkv_hi + gr + 64);    // K hi
            cp_async16(sbase + AT_TILE + soff,     qkv_lo + gr + 64);    // K lo
            cp_async16(sbase + 2 * AT_TILE + soff, qkv_hi + gr + 128);   // V hi
            cp_async16(sbase + 3 * AT_TILE + soff, qkv_lo + gr + 128);   // V lo
        }
        CP_COMMIT();
    };

    float m2[2] = {-1e30f, -1e30f}, l[2] = {0.f, 0.f};
    float o[8][4];
#pragma unroll
    for (int dt = 0; dt < 8; dt++)
#pragma unroll
        for (int j = 0; j < 4; j++) o[dt][j] = 0.0f;

    const int rbase = 128 * it + 16 * (wid & 3) + 64 * (wid >> 2);
    const int g  = lane >> 2;
    const int t2 = (lane & 3) * 2;
    const uint32_t koff = (uint32_t)(((lane >> 4) * 8 + (lane & 7)) * AT_STRIDE +
                                     ((lane >> 3) & 1) * 8) * 2;
    const uint32_t voff = (uint32_t)((lane & 15) * AT_STRIDE + (lane >> 4) * 8) * 2;

    const int jt_max = 2 * it + 2;
    load_kv(0, 0);

    for (int jt = 0; jt < jt_max; jt++) {
        const bool pref = (jt + 1 < jt_max);
        if (pref) load_kv((jt + 1) & 1, jt + 1);
        if (pref) CP_WAIT1(); else CP_WAIT0();
        __syncthreads();

        const uint32_t KH = sb + (jt & 1) * AT_STAGE;
        const uint32_t KL = KH + AT_TILE;
        const uint32_t VH = KH + 2 * AT_TILE;
        const uint32_t VL = KH + 3 * AT_TILE;

        // ---- S = Q K^T (hoisted hi/lo fragments) ----
        float s[8][4];
#pragma unroll
        for (int nt = 0; nt < 8; nt++)
#pragma unroll
            for (int j = 0; j < 4; j++) s[nt][j] = 0.0f;

#pragma unroll
        for (int ks = 0; ks < 4; ks++) {
            uint32_t kh[4][4], kl[4][4];
#pragma unroll
            for (int np = 0; np < 4; np++) {
                uint32_t bo = koff + (uint32_t)(np * 16 * AT_STRIDE + ks * 16) * 2;
                ldsm_x4(KH + bo, kh[np]);
                ldsm_x4(KL + bo, kl[np]);
            }
#pragma unroll
            for (int np = 0; np < 4; np++) {
                mma16816(s[2 * np],     qh[ks], kh[np][0], kh[np][1]);
                mma16816(s[2 * np + 1], qh[ks], kh[np][2], kh[np][3]);
            }
#pragma unroll
            for (int np = 0; np < 4; np++) {
                mma16816(s[2 * np],     qh[ks], kl[np][0], kl[np][1]);
                mma16816(s[2 * np + 1], qh[ks], kl[np][2], kl[np][3]);
            }
#pragma unroll
            for (int np = 0; np < 4; np++) {
                mma16816(s[2 * np],     ql[ks], kh[np][0], kh[np][1]);
                mma16816(s[2 * np + 1], ql[ks], kh[np][2], kh[np][3]);
            }
        }

        // ---- scale (+ causal mask on diagonal tiles) ----
        const bool diag = (jt >= 2 * it);
#pragma unroll
        for (int nt = 0; nt < 8; nt++)
#pragma unroll
            for (int j = 0; j < 4; j++) {
                float t = s[nt][j] * SCALE2;
                if (diag) {
                    int col = jt * 64 + nt * 8 + t2 + (j & 1);
                    int row = rbase + g + 8 * (j >> 1);
                    if (col > row) t = -1e30f;
                }
                s[nt][j] = t;
            }

        // ---- online softmax ----
        float rmax[2] = {-1e30f, -1e30f};
#pragma unroll
        for (int nt = 0; nt < 8; nt++) {
            rmax[0] = fmaxf(rmax[0], fmaxf(s[nt][0], s[nt][1]));
            rmax[1] = fmaxf(rmax[1], fmaxf(s[nt][2], s[nt][3]));
        }
#pragma unroll
        for (int off = 1; off <= 2; off <<= 1) {
            rmax[0] = fmaxf(rmax[0], __shfl_xor_sync(0xffffffffu, rmax[0], off));
            rmax[1] = fmaxf(rmax[1], __shfl_xor_sync(0xffffffffu, rmax[1], off));
        }
        float alpha[2], rsum[2];
#pragma unroll
        for (int r = 0; r < 2; r++) {
            float mnew = fmaxf(m2[r], rmax[r]);
            alpha[r] = ex2(m2[r] - mnew);
            m2[r] = mnew;
            rsum[r] = 0.f;
        }
#pragma unroll
        for (int nt = 0; nt < 8; nt++) {
            s[nt][0] = ex2(s[nt][0] - m2[0]);
            s[nt][1] = ex2(s[nt][1] - m2[0]);
            s[nt][2] = ex2(s[nt][2] - m2[1]);
            s[nt][3] = ex2(s[nt][3] - m2[1]);
            rsum[0] += s[nt][0] + s[nt][1];
            rsum[1] += s[nt][2] + s[nt][3];
        }
#pragma unroll
        for (int off = 1; off <= 2; off <<= 1) {
            rsum[0] += __shfl_xor_sync(0xffffffffu, rsum[0], off);
            rsum[1] += __shfl_xor_sync(0xffffffffu, rsum[1], off);
        }
#pragma unroll
        for (int r = 0; r < 2; r++) l[r] = l[r] * alpha[r] + rsum[r];
#pragma unroll
        for (int dt = 0; dt < 8; dt++) {
            o[dt][0] *= alpha[0];
            o[dt][1] *= alpha[0];
            o[dt][2] *= alpha[1];
            o[dt][3] *= alpha[1];
        }

        // ---- pack P into A-fragments (hi + lo) ----
        uint32_t ph[4][4], pl[4][4];
#pragma unroll
        for (int ks = 0; ks < 4; ks++) {
#pragma unroll
            for (int half = 0; half < 2; half++) {
                int nt = 2 * ks + half;
                float p0 = s[nt][0], p1 = s[nt][1], p2 = s[nt][2], p3 = s[nt][3];
                float h0 = __bfloat162float(__float2bfloat16_rn(p0));
                float h1 = __bfloat162float(__float2bfloat16_rn(p1));
                float h2 = __bfloat162float(__float2bfloat16_rn(p2));
                float h3 = __bfloat162float(__float2bfloat16_rn(p3));
                ph[ks][2 * half]     = pack_bf16(h0, h1);
                ph[ks][2 * half + 1] = pack_bf16(h2, h3);
                pl[ks][2 * half]     = pack_bf16(p0 - h0, p1 - h1);
                pl[ks][2 * half + 1] = pack_bf16(p2 - h2, p3 - h3);
            }
        }

        // ---- O += P V (hoisted hi/lo V fragments; ldmatrix.trans) ----
#pragma unroll
        for (int ks = 0; ks < 4; ks++) {
            uint32_t vh[4][4], vl[4][4];
#pragma unroll
            for (int np = 0; np < 4; np++) {
                uint32_t bo = voff + (uint32_t)(ks * 16 * AT_STRIDE + np * 16) * 2;
                ldsm_x4_t(VH + bo, vh[np]);
                ldsm_x4_t(VL + bo, vl[np]);
            }
#pragma unroll
            for (int np = 0; np < 4; np++) {
                mma16816(o[2 * np],     ph[ks], vh[np][0], vh[np][1]);
                mma16816(o[2 * np + 1], ph[ks], vh[np][2], vh[np][3]);
            }
#pragma unroll
            for (int np = 0; np < 4; np++) {
                mma16816(o[2 * np],     ph[ks], vl[np][0], vl[np][1]);
                mma16816(o[2 * np + 1], ph[ks], vl[np][2], vl[np][3]);
            }
#pragma unroll
            for (int np = 0; np < 4; np++) {
                mma16816(o[2 * np],     pl[ks], vh[np][0], vh[np][1]);
                mma16816(o[2 * np + 1], pl[ks], vh[np][2], vh[np][3]);
            }
        }
        __syncthreads();
    }

    // ---- epilogue: O/l -> att hi/lo ----
    float inv0 = 1.0f / l[0], inv1 = 1.0f / l[1];
#pragma unroll
    for (int dt = 0; dt < 8; dt++) {
        int col = h * 64 + dt * 8 + t2;
        size_t i0 = ((size_t)b * SEQ + rbase + g) * EMB + col;
        size_t i1 = ((size_t)b * SEQ + rbase + g + 8) * EMB + col;
        float v00 = o[dt][0] * inv0, v01 = o[dt][1] * inv0;
        float v10 = o[dt][2] * inv1, v11 = o[dt][3] * inv1;
        float h00 = __bfloat162float(__float2bfloat16_rn(v00));
        float h01 = __bfloat162float(__float2bfloat16_rn(v01));
        float h10 = __bfloat162float(__float2bfloat16_rn(v10));
        float h11 = __bfloat162float(__float2bfloat16_rn(v11));
        *(uint32_t*)(att_hi + i0) = pack_bf16(h00, h01);
        *(uint32_t*)(att_lo + i0) = pack_bf16(v00 - h00, v01 - h01);
        *(uint32_t*)(att_hi + i1) = pack_bf16(h10, h11);
        *(uint32_t*)(att_lo + i1) = pack_bf16(v10 - h10, v11 - h11);
    }
}

// ---------------------------------------------------------------------------
// Launch
// ---------------------------------------------------------------------------
extern "C" void kernel_launch(void* const* d_in, const int* in_sizes, int n_in,
                              void* d_out, int out_size) {
    const float* x      = (const float*)d_in[0];
    const float* w_qkv  = (const float*)d_in[1];
    const float* w_out  = (const float*)d_in[2];
    const float* b_out  = (const float*)d_in[3];
    float* out = (float*)d_out;

    __nv_bfloat16 *x_hi, *x_lo, *wq_hi, *wq_lo, *wo_hi, *wo_lo;
    __nv_bfloat16 *qkv_hi, *qkv_lo, *a_hi, *a_lo;
    cudaGetSymbolAddress((void**)&x_hi,   g_x_hi);
    cudaGetSymbolAddress((void**)&x_lo,   g_x_lo);
    cudaGetSymbolAddress((void**)&wq_hi,  g_wqkv_hi);
    cudaGetSymbolAddress((void**)&wq_lo,  g_wqkv_lo);
    cudaGetSymbolAddress((void**)&wo_hi,  g_wout_hi);
    cudaGetSymbolAddress((void**)&wo_lo,  g_wout_lo);
    cudaGetSymbolAddress((void**)&qkv_hi, g_qkv_hi);
    cudaGetSymbolAddress((void**)&qkv_lo, g_qkv_lo);
    cudaGetSymbolAddress((void**)&a_hi,   g_att_hi);
    cudaGetSymbolAddress((void**)&a_lo,   g_att_lo);

    cudaFuncSetAttribute(attn_mma,
                         cudaFuncAttributeMaxDynamicSharedMemorySize, ATTN_SMEM);
    cudaFuncSetAttribute((const void*)gemm_mma<false, true>,
                         cudaFuncAttributeMaxDynamicSharedMemorySize, GEMM_SMEM);
    cudaFuncSetAttribute((const void*)gemm_mma<true, false>,
                         cudaFuncAttributeMaxDynamicSharedMemorySize, GEMM_SMEM);

    // 0) bf16 hi/lo splits of inputs
    {
        int n4 = ROWS * EMB / 4;
        split_bf16<<<(n4 + 255) / 256, 256>>>((const float4*)x,
            (__nv_bfloat162*)x_hi, (__nv_bfloat162*)x_lo, n4);
        n4 = F3 * EMB / 4;
        split_bf16<<<(n4 + 255) / 256, 256>>>((const float4*)w_qkv,
            (__nv_bfloat162*)wq_hi, (__nv_bfloat162*)wq_lo, n4);
        n4 = EMB * EMB / 4;
        split_bf16<<<(n4 + 255) / 256, 256>>>((const float4*)w_out,
            (__nv_bfloat162*)wo_hi, (__nv_bfloat162*)wo_lo, n4);
    }

    // 1) QKV projection -> bf16 hi/lo qkv directly
    gemm_mma<false, true><<<dim3(F3 / 128, ROWS / 256), 256, GEMM_SMEM>>>(
        x_hi, x_lo, wq_hi, wq_lo, nullptr, nullptr, qkv_hi, qkv_lo, F3, EMB);

    // 2) Tensor-core causal flash attention -> att hi/lo
    attn_mma<<<dim3(SEQ / 128, NH, BS), 256, ATTN_SMEM>>>(qkv_hi, qkv_lo, a_hi, a_lo);

    // 3) Output projection + bias -> fp32 out
    gemm_mma<true, false><<<dim3(EMB / 128, ROWS / 256), 256, GEMM_SMEM>>>(
        a_hi, a_lo, wo_hi, wo_lo, b_out, out, nullptr, nullptr, EMB, EMB);
}